// round 4
// baseline (speedup 1.0000x reference)
#include <cuda_runtime.h>
#include <cuda_bf16.h>
#include <mma.h>
#include <cstdint>

using namespace nvcuda;

#define NN  100000
#define EE  1000000
#define IND 128
#define HID 256
#define GG  64
#define BN_EPS 1e-5f

#define TILE_M 128
#define NBLK   ((NN + TILE_M - 1) / TILE_M)   // 782

// ---------------- scratch (static device globals; no allocation) ----------------
__device__ float g_agg[NN * IND];            // neighbor feature sums
__device__ int   g_deg[NN];
__device__ float g_poolraw[GG * HID];        // per-graph sums of relu(conv), pre-BN
__device__ int   g_cnt[GG];
__device__ float g_bnstats[8 * HID];
__device__ float g_z1[GG * HID];
__device__ float g_z2[GG * HID];
__device__ float g_p[GG * HID];
// bf16 W images, row-major [K=256][N=256]
__device__ __nv_bfloat16 g_Bhi[256 * 256];
__device__ __nv_bfloat16 g_Blo[256 * 256];

// ---------------- helpers ----------------
__device__ __forceinline__ void redF4(float4* addr, float4 v) {
    asm volatile("red.global.add.v4.f32 [%0], {%1, %2, %3, %4};"
                 :: "l"(addr), "f"(v.x), "f"(v.y), "f"(v.z), "f"(v.w) : "memory");
}
__device__ __forceinline__ void redF1(float* addr, float v) {
    asm volatile("red.global.add.f32 [%0], %1;" :: "l"(addr), "f"(v) : "memory");
}
__device__ __forceinline__ uint32_t bfu(__nv_bfloat16 h) {
    return (uint32_t)__bfloat16_as_ushort(h);
}

// ---------------- K0: zero scratch ----------------
__global__ void zero_kernel() {
    int idx = blockIdx.x * blockDim.x + threadIdx.x;
    if (idx < NN * IND / 4)
        ((float4*)g_agg)[idx] = make_float4(0.f, 0.f, 0.f, 0.f);
    if (idx < NN) g_deg[idx] = 0;
    if (idx < GG * HID) g_poolraw[idx] = 0.f;
    if (idx < GG) g_cnt[idx] = 0;
    if (idx < 6 * HID) g_bnstats[idx] = 0.f;
}

// ---------------- K0b: per-graph node counts ----------------
__global__ void count_kernel(const int* __restrict__ graph_id) {
    __shared__ int cnt[GG];
    int t = threadIdx.x;
    if (t < GG) cnt[t] = 0;
    __syncthreads();
    for (int i = blockIdx.x * blockDim.x + t; i < NN; i += gridDim.x * blockDim.x)
        atomicAdd(&cnt[__ldg(&graph_id[i])], 1);
    __syncthreads();
    if (t < GG && cnt[t]) atomicAdd(&g_cnt[t], cnt[t]);
}

// ---------------- K1: edge gather + scatter-add (warp per edge) ----------------
__global__ void scatter_kernel(const float* __restrict__ feat,
                               const int* __restrict__ src,
                               const int* __restrict__ dst) {
    int t = blockIdx.x * blockDim.x + threadIdx.x;
    int e = t >> 5;
    if (e >= EE) return;
    int lane = t & 31;
    int s = __ldg(&src[e]);
    int d = __ldg(&dst[e]);
    float4 v = __ldg(((const float4*)(feat + (size_t)s * IND)) + lane);
    redF4(((float4*)(g_agg + (size_t)d * IND)) + lane, v);
    if (lane == 0) atomicAdd(&g_deg[d], 1);
}

// ---------------- Kw: W -> bf16 hi/lo row-major images ----------------
__global__ void wprep_kernel(const float* __restrict__ W_self,
                             const float* __restrict__ W_neigh) {
    int k = blockIdx.x;    // 0..255  (global K)
    int n = threadIdx.x;   // 0..255  (output col)
    float w = (k < IND) ? W_self[k * HID + n] : W_neigh[(k - IND) * HID + n];
    __nv_bfloat16 hi = __float2bfloat16(w);
    __nv_bfloat16 lo = __float2bfloat16(w - __bfloat162float(hi));
    g_Bhi[k * 256 + n] = hi;
    g_Blo[k * 256 + n] = lo;
}

// ---------------- K2: WMMA split-bf16 GEMM + relu + BN stats + pooling ----------
// smem layout (bytes from dynamic smem base):
//  stage s (s=0,1) at s*37888:
//    Ahi [128][40] bf16  @ +0      (10240)
//    Alo [128][40] bf16  @ +10240
//    Bhi [32][136] bf16  @ +20480  (8704)
//    Blo [32][136] bf16  @ +29184
//  C float[128][132] aliases offset 0 (used after mainloop + sync)
#define ST_SZ    37888
#define AOF_LO   10240
#define AOF_BH   20480
#define AOF_BL   29184
#define OFF_BSH  75776
#define OFF_INVD 76288
#define OFF_GIDS 76800
#define OFF_GRNG 77312
#define OFF_RS   77376
#define OFF_RQ   79424
#define DYN_SMEM 81472

__global__ __launch_bounds__(512, 1) void conv_wmma_kernel(
    const float* __restrict__ feat, const float* __restrict__ b_conv,
    const int* __restrict__ graph_id) {
    extern __shared__ char p0[];
    float* s_bsh  = (float*)(p0 + OFF_BSH);
    float* s_invd = (float*)(p0 + OFF_INVD);
    int*   s_gids = (int*)(p0 + OFF_GIDS);
    int*   s_grng = (int*)(p0 + OFF_GRNG);
    float* s_rs   = (float*)(p0 + OFF_RS);
    float* s_rq   = (float*)(p0 + OFF_RQ);

    int tid = threadIdx.x;
    int wid = tid >> 5;
    int row0 = blockIdx.x * TILE_M;
    int n0g = blockIdx.y * 128;          // this block's output-column base

    if (tid < 128) {
        s_bsh[tid] = b_conv[n0g + tid];
        int node = row0 + tid;
        float dg = 1.f;
        int gid = -1;
        if (node < NN) {
            dg = fmaxf((float)g_deg[node], 1.f);
            gid = __ldg(&graph_id[node]);
        }
        s_invd[tid] = 1.f / dg;
        s_gids[tid] = gid;
    }
    __syncthreads();
    if (tid == 0) {
        int lo = s_gids[0], hi = lo;
#pragma unroll 1
        for (int i = 1; i < TILE_M; i++)
            if (s_gids[i] >= 0) hi = s_gids[i];
        s_grng[0] = lo; s_grng[1] = hi;
    }

    // accumulators: warp tile 32x32 = 2x2 wmma 16x16 frags
    wmma::fragment<wmma::accumulator, 16, 16, 16, float> acc[2][2];
#pragma unroll
    for (int m = 0; m < 2; m++)
#pragma unroll
        for (int n = 0; n < 2; n++) wmma::fill_fragment(acc[m][n], 0.f);

    int wm = (wid >> 2) * 32;   // warp row offset
    int wn = (wid & 3) * 32;    // warp col offset

    // register prefetch state
    float4 pa[2];
    uint4 pbh, pbl;

    auto load_g = [&](int kc) {
#pragma unroll
        for (int it = 0; it < 2; it++) {
            int e = tid + it * 512;
            int r = e >> 3, k4 = e & 7;
            int node = row0 + r;
            float4 v = make_float4(0.f, 0.f, 0.f, 0.f);
            if (node < NN) {
                if (kc < 4) {
                    v = __ldg((const float4*)(feat + (size_t)node * IND + kc * 32 + k4 * 4));
                } else {
                    v = *(const float4*)(g_agg + (size_t)node * IND + (kc - 4) * 32 + k4 * 4);
                    float s = s_invd[r];
                    v.x *= s; v.y *= s; v.z *= s; v.w *= s;
                }
            }
            pa[it] = v;
        }
        int r = tid >> 4, c = tid & 15;
        int kk = kc * 32 + r;
        pbh = *(const uint4*)(g_Bhi + kk * 256 + n0g + c * 8);
        pbl = *(const uint4*)(g_Blo + kk * 256 + n0g + c * 8);
    };
    auto store_s = [&](int buf) {
        char* st = p0 + buf * ST_SZ;
#pragma unroll
        for (int it = 0; it < 2; it++) {
            int e = tid + it * 512;
            int r = e >> 3, k4 = e & 7;
            float4 v = pa[it];
            __nv_bfloat16 h0 = __float2bfloat16(v.x);
            __nv_bfloat16 h1 = __float2bfloat16(v.y);
            __nv_bfloat16 h2 = __float2bfloat16(v.z);
            __nv_bfloat16 h3 = __float2bfloat16(v.w);
            __nv_bfloat16 l0 = __float2bfloat16(v.x - __bfloat162float(h0));
            __nv_bfloat16 l1 = __float2bfloat16(v.y - __bfloat162float(h1));
            __nv_bfloat16 l2 = __float2bfloat16(v.z - __bfloat162float(h2));
            __nv_bfloat16 l3 = __float2bfloat16(v.w - __bfloat162float(h3));
            uint2 hu = make_uint2((bfu(h1) << 16) | bfu(h0), (bfu(h3) << 16) | bfu(h2));
            uint2 lu = make_uint2((bfu(l1) << 16) | bfu(l0), (bfu(l3) << 16) | bfu(l2));
            *(uint2*)(st + r * 80 + k4 * 8) = hu;
            *(uint2*)(st + AOF_LO + r * 80 + k4 * 8) = lu;
        }
        int r = tid >> 4, c = tid & 15;
        *(uint4*)(st + AOF_BH + r * 272 + c * 16) = pbh;
        *(uint4*)(st + AOF_BL + r * 272 + c * 16) = pbl;
    };
    auto compute = [&](int buf) {
        char* st = p0 + buf * ST_SZ;
        const __nv_bfloat16* Ah = (const __nv_bfloat16*)st;
        const __nv_bfloat16* Al = (const __nv_bfloat16*)(st + AOF_LO);
        const __nv_bfloat16* Bh = (const __nv_bfloat16*)(st + AOF_BH);
        const __nv_bfloat16* Bl = (const __nv_bfloat16*)(st + AOF_BL);
#pragma unroll
        for (int ks = 0; ks < 2; ks++) {
            wmma::fragment<wmma::matrix_a, 16, 16, 16, __nv_bfloat16, wmma::row_major> ah[2], al[2];
            wmma::fragment<wmma::matrix_b, 16, 16, 16, __nv_bfloat16, wmma::row_major> bh[2], bl[2];
#pragma unroll
            for (int m = 0; m < 2; m++) {
                wmma::load_matrix_sync(ah[m], Ah + (wm + m * 16) * 40 + ks * 16, 40);
                wmma::load_matrix_sync(al[m], Al + (wm + m * 16) * 40 + ks * 16, 40);
            }
#pragma unroll
            for (int n = 0; n < 2; n++) {
                wmma::load_matrix_sync(bh[n], Bh + (ks * 16) * 136 + wn + n * 16, 136);
                wmma::load_matrix_sync(bl[n], Bl + (ks * 16) * 136 + wn + n * 16, 136);
            }
#pragma unroll
            for (int m = 0; m < 2; m++)
#pragma unroll
                for (int n = 0; n < 2; n++) {
                    wmma::mma_sync(acc[m][n], ah[m], bh[n], acc[m][n]);
                    wmma::mma_sync(acc[m][n], ah[m], bl[n], acc[m][n]);
                    wmma::mma_sync(acc[m][n], al[m], bh[n], acc[m][n]);
                }
        }
    };

    // -------- main loop: 8 K-chunks of 32, double-buffered --------
    load_g(0);
    store_s(0);
    __syncthreads();
#pragma unroll 1
    for (int kc = 0; kc < 8; kc++) {
        if (kc < 7) load_g(kc + 1);
        compute(kc & 1);
        if (kc < 7) store_s((kc + 1) & 1);
        __syncthreads();
    }

    // -------- epilogue: C to smem, bias+relu, BN stats, pooling --------
    float* C = (float*)p0;   // [128][132], aliases tile buffers (safe post-sync)
#pragma unroll
    for (int m = 0; m < 2; m++)
#pragma unroll
        for (int n = 0; n < 2; n++)
            wmma::store_matrix_sync(C + (wm + m * 16) * 132 + wn + n * 16,
                                    acc[m][n], 132, wmma::mem_row_major);
    __syncthreads();

    int col = tid & 127, q = tid >> 7;    // quarter of rows
    {
        float sum = 0.f, sq = 0.f;
        float b = s_bsh[col];
#pragma unroll 8
        for (int rr = q * 32; rr < q * 32 + 32; rr++) {
            float v = C[rr * 132 + col] + b;
            v = (s_gids[rr] >= 0) ? fmaxf(v, 0.f) : 0.f;
            C[rr * 132 + col] = v;
            sum += v; sq += v * v;
        }
        s_rs[q * 128 + col] = sum;
        s_rq[q * 128 + col] = sq;
    }
    __syncthreads();
    if (tid < 128) {
        float s = s_rs[tid] + s_rs[128 + tid] + s_rs[256 + tid] + s_rs[384 + tid];
        redF1(&g_bnstats[n0g + tid], s);
    } else if (tid < 256) {
        int c2 = tid - 128;
        float qq = s_rq[c2] + s_rq[128 + c2] + s_rq[256 + c2] + s_rq[384 + c2];
        redF1(&g_bnstats[256 + n0g + c2], qq);
    }
    int glo = s_grng[0], ghi = s_grng[1];
#pragma unroll 1
    for (int g = glo; g <= ghi; g++) {
        float pp = 0.f;
#pragma unroll 8
        for (int rr = q * 32; rr < q * 32 + 32; rr++)
            if (s_gids[rr] == g) pp += C[rr * 132 + col];
        __syncthreads();
        s_rs[q * 128 + col] = pp;
        __syncthreads();
        if (tid < 128) {
            float s = s_rs[tid] + s_rs[128 + tid] + s_rs[256 + tid] + s_rs[384 + tid];
            redF1(&g_poolraw[g * HID + n0g + tid], s);
        }
    }
}

// ---------------- K2b: fold BN stats into per-column scale/shift ----------------
__global__ void bn_scale_kernel(const float* __restrict__ gamma,
                                const float* __restrict__ beta) {
    int c = threadIdx.x;
    float mean = g_bnstats[c] * (1.0f / NN);
    float var  = g_bnstats[256 + c] * (1.0f / NN) - mean * mean;
    float sc = gamma[c] * rsqrtf(var + BN_EPS);
    g_bnstats[1536 + c] = sc;
    g_bnstats[1792 + c] = beta[c] - mean * sc;
}

// ---------------- K4: z1 = relu(pooled @ W_lp + b) + stats ----------------
__global__ __launch_bounds__(HID) void lp1_kernel(const float* __restrict__ W_lp,
                                                  const float* __restrict__ b_lp) {
    __shared__ float row[HID];
    int g = blockIdx.x, c = threadIdx.x;
    float cntf = (float)g_cnt[g];
    row[c] = fmaf(g_poolraw[g * HID + c], g_bnstats[1536 + c],
                  cntf * g_bnstats[1792 + c]);
    __syncthreads();
    float acc = b_lp[c];
#pragma unroll 8
    for (int k = 0; k < HID; k++) acc = fmaf(row[k], __ldg(&W_lp[k * HID + c]), acc);
    float r = fmaxf(acc, 0.f);
    g_z1[g * HID + c] = r;
    atomicAdd(&g_bnstats[512 + c], r);
    atomicAdd(&g_bnstats[768 + c], r * r);
}

// ---------------- K5: BN(z1) -> p, z2 = relu(p @ W_lp + b) + stats ----------------
__global__ __launch_bounds__(HID) void lp2_kernel(const float* __restrict__ W_lp,
                                                  const float* __restrict__ b_lp,
                                                  const float* __restrict__ gamma,
                                                  const float* __restrict__ beta,
                                                  float* __restrict__ out_p) {
    __shared__ float row[HID];
    int g = blockIdx.x, c = threadIdx.x;
    float r = g_z1[g * HID + c];
    float mean = g_bnstats[512 + c] * (1.f / GG);
    float var  = g_bnstats[768 + c] * (1.f / GG) - mean * mean;
    float p = (r - mean) * rsqrtf(var + BN_EPS) * gamma[c] + beta[c];
    out_p[g * HID + c] = p;
    row[c] = p;
    __syncthreads();
    float acc = b_lp[c];
#pragma unroll 8
    for (int k = 0; k < HID; k++) acc = fmaf(row[k], __ldg(&W_lp[k * HID + c]), acc);
    float r2 = fmaxf(acc, 0.f);
    g_z2[g * HID + c] = r2;
    atomicAdd(&g_bnstats[1024 + c], r2);
    atomicAdd(&g_bnstats[1280 + c], r2 * r2);
}

// ---------------- K6: BN(z2) + log_softmax ----------------
__global__ __launch_bounds__(HID) void lp3_kernel(const float* __restrict__ gamma,
                                                  const float* __restrict__ beta,
                                                  float* __restrict__ out) {
    __shared__ float buf[HID];
    int g = blockIdx.x, c = threadIdx.x;
    float r = g_z2[g * HID + c];
    float mean = g_bnstats[1024 + c] * (1.f / GG);
    float var  = g_bnstats[1280 + c] * (1.f / GG) - mean * mean;
    float o = (r - mean) * rsqrtf(var + BN_EPS) * gamma[c] + beta[c];
    buf[c] = o;
    __syncthreads();
    for (int s = 128; s > 0; s >>= 1) {
        if (c < s) buf[c] = fmaxf(buf[c], buf[c + s]);
        __syncthreads();
    }
    float m = buf[0];
    __syncthreads();
    float e = expf(o - m);
    buf[c] = e;
    __syncthreads();
    for (int s = 128; s > 0; s >>= 1) {
        if (c < s) buf[c] += buf[c + s];
        __syncthreads();
    }
    float lse = logf(buf[0]);
    out[g * HID + c] = o - m - lse;
}

// ---------------- launch ----------------
extern "C" void kernel_launch(void* const* d_in, const int* in_sizes, int n_in,
                              void* d_out, int out_size) {
    const float* feat       = (const float*)d_in[0];
    const float* W_self     = (const float*)d_in[1];
    const float* W_neigh    = (const float*)d_in[2];
    const float* b_conv     = (const float*)d_in[3];
    const float* gamma_conv = (const float*)d_in[4];
    const float* beta_conv  = (const float*)d_in[5];
    const float* W_lp       = (const float*)d_in[6];
    const float* b_lp       = (const float*)d_in[7];
    const float* gamma_lp   = (const float*)d_in[8];
    const float* beta_lp    = (const float*)d_in[9];
    const int*   src        = (const int*)d_in[10];
    const int*   dst        = (const int*)d_in[11];
    const int*   graph_id   = (const int*)d_in[12];
    float* out = (float*)d_out;

    float* out_p;
    if (out_size >= 2 * GG * HID) {
        out_p = out + GG * HID;
    } else {
        void* pp = nullptr;
        cudaGetSymbolAddress(&pp, g_p);
        out_p = (float*)pp;
    }

    cudaFuncSetAttribute(conv_wmma_kernel,
                         cudaFuncAttributeMaxDynamicSharedMemorySize, DYN_SMEM);

    zero_kernel<<<(NN * IND / 4 + 255) / 256, 256>>>();
    count_kernel<<<128, 1024>>>(graph_id);
    wprep_kernel<<<256, 256>>>(W_self, W_neigh);
    scatter_kernel<<<(EE * 32 + 255) / 256, 256>>>(feat, src, dst);
    dim3 cgrid(NBLK, 2);
    conv_wmma_kernel<<<cgrid, 512, DYN_SMEM>>>(feat, b_conv, graph_id);
    bn_scale_kernel<<<1, HID>>>(gamma_conv, beta_conv);
    lp1_kernel<<<GG, HID>>>(W_lp, b_lp);
    lp2_kernel<<<GG, HID>>>(W_lp, b_lp, gamma_lp, beta_lp, out_p);
    lp3_kernel<<<GG, HID>>>(gamma_lp, beta_lp, out);
}

// round 5
// speedup vs baseline: 1.0823x; 1.0823x over previous
#include <cuda_runtime.h>
#include <cstdint>

#define NN  100000
#define EE  1000000
#define IND 128
#define HID 256
#define GG  64
#define BN_EPS 1e-5f

// ---------------- scratch (static device globals; no allocation) ----------------
__device__ float g_agg[NN * IND];            // neighbor feature sums (written once, no init)
__device__ int   g_deg[NN];
__device__ int   g_ptr[NN];                  // CSR exclusive prefix
__device__ int   g_cur[NN];                  // fill cursors
__device__ int   g_esrc[EE];                 // CSR src lists
__device__ float g_poolraw[GG * HID];        // per-graph sums of relu(conv), pre-BN
__device__ int   g_cnt[GG];
__device__ float g_bnstats[8 * HID];
__device__ float g_z1[GG * HID];
__device__ float g_z2[GG * HID];
__device__ float g_p[GG * HID];

// ---------------- helpers ----------------
__device__ __forceinline__ unsigned long long pack2(float lo, float hi) {
    unsigned long long r;
    asm("mov.b64 %0, {%1, %2};" : "=l"(r) : "f"(lo), "f"(hi));
    return r;
}
__device__ __forceinline__ float2 unpack2(unsigned long long v) {
    float2 f;
    asm("mov.b64 {%0, %1}, %2;" : "=f"(f.x), "=f"(f.y) : "l"(v));
    return f;
}
__device__ __forceinline__ void fma2(unsigned long long& acc, unsigned long long a,
                                     unsigned long long b) {
    asm("fma.rn.f32x2 %0, %1, %2, %0;" : "+l"(acc) : "l"(a), "l"(b));
}
__device__ __forceinline__ void redF1(float* addr, float v) {
    asm volatile("red.global.add.f32 [%0], %1;" :: "l"(addr), "f"(v) : "memory");
}
__device__ __forceinline__ void redI1(int* addr, int v) {
    asm volatile("red.global.add.s32 [%0], %1;" :: "l"(addr), "r"(v) : "memory");
}

// ---------------- K0: zero small scratch ----------------
__global__ void zero_kernel() {
    int idx = blockIdx.x * blockDim.x + threadIdx.x;
    if (idx < NN) g_deg[idx] = 0;
    if (idx < GG * HID) g_poolraw[idx] = 0.f;
    if (idx < GG) g_cnt[idx] = 0;
    if (idx < 6 * HID) g_bnstats[idx] = 0.f;
}

// ---------------- K0b: per-graph node counts ----------------
__global__ void count_kernel(const int* __restrict__ graph_id) {
    __shared__ int cnt[GG];
    int t = threadIdx.x;
    if (t < GG) cnt[t] = 0;
    __syncthreads();
    for (int i = blockIdx.x * blockDim.x + t; i < NN; i += gridDim.x * blockDim.x)
        atomicAdd(&cnt[__ldg(&graph_id[i])], 1);
    __syncthreads();
    if (t < GG && cnt[t]) atomicAdd(&g_cnt[t], cnt[t]);
}

// ---------------- CSR phase 1: degree count ----------------
__global__ void deg_kernel(const int* __restrict__ dst) {
    int e = blockIdx.x * blockDim.x + threadIdx.x;
    if (e < EE) redI1(&g_deg[__ldg(&dst[e])], 1);
}

// ---------------- CSR phase 2: exclusive scan (single block) ----------------
#define SCAN_T 1024
#define PER_T  ((NN + SCAN_T - 1) / SCAN_T)   // 98
__global__ __launch_bounds__(SCAN_T) void scan_kernel() {
    __shared__ int part[SCAN_T];
    int t = threadIdx.x;
    int lo = t * PER_T, hi = min(NN, lo + PER_T);
    int s = 0;
    for (int i = lo; i < hi; i++) s += g_deg[i];
    part[t] = s;
    __syncthreads();
    // Hillis-Steele inclusive scan
    for (int off = 1; off < SCAN_T; off <<= 1) {
        int v = (t >= off) ? part[t - off] : 0;
        __syncthreads();
        part[t] += v;
        __syncthreads();
    }
    int base = (t == 0) ? 0 : part[t - 1];
    for (int i = lo; i < hi; i++) {
        g_ptr[i] = base;
        g_cur[i] = base;
        base += g_deg[i];
    }
}

// ---------------- CSR phase 3: fill ----------------
__global__ void fill_kernel(const int* __restrict__ src,
                            const int* __restrict__ dst) {
    int e = blockIdx.x * blockDim.x + threadIdx.x;
    if (e >= EE) return;
    int d = __ldg(&dst[e]);
    int pos = atomicAdd(&g_cur[d], 1);
    g_esrc[pos] = __ldg(&src[e]);
}

// ---------------- K1: gather-aggregate (warp per node, no atomics) ----------------
__global__ __launch_bounds__(256) void agg_kernel(const float* __restrict__ feat) {
    int t = blockIdx.x * blockDim.x + threadIdx.x;
    int node = t >> 5;
    if (node >= NN) return;
    int lane = t & 31;
    int beg = __ldg(&g_ptr[node]);
    int d = __ldg(&g_deg[node]);
    float4 acc = make_float4(0.f, 0.f, 0.f, 0.f);
    for (int i = 0; i < d; i++) {
        int s = __ldg(&g_esrc[beg + i]);
        float4 v = __ldg(((const float4*)(feat + (size_t)s * IND)) + lane);
        acc.x += v.x; acc.y += v.y; acc.z += v.z; acc.w += v.w;
    }
    ((float4*)(g_agg + (size_t)node * IND))[lane] = acc;
}

// ---------------- K2: fused GEMM  h = relu([feat | agg/deg] @ [Wself;Wneigh] + b)
//                 + BN column statistics + per-graph raw pooling ----------------
__global__ __launch_bounds__(256, 2) void conv_gemm_kernel(
    const float* __restrict__ feat, const float* __restrict__ W_self,
    const float* __restrict__ W_neigh, const float* __restrict__ b_conv,
    const int* __restrict__ graph_id) {
    __shared__ float As[32][72];    // A tile, transposed [k][row], padded
    __shared__ float Ws[32][256];   // W tile [k][col]  (reused for reductions)
    __shared__ float invd[64];
    __shared__ float bsh[256];
    __shared__ int   gids[64];
    __shared__ int   grange[2];

    int tid = threadIdx.x;
    int row0 = blockIdx.x * 64;
    bsh[tid] = b_conv[tid];
    if (tid < 64) {
        int node = row0 + tid;
        float dg = 1.f;
        int gid = -1;
        if (node < NN) {
            dg = fmaxf((float)g_deg[node], 1.f);
            gid = __ldg(&graph_id[node]);
        }
        invd[tid] = 1.f / dg;
        gids[tid] = gid;
    }
    int ty = tid >> 5;   // row group (8)
    int tx = tid & 31;   // col group (32)

    unsigned long long acc[8][4];
#pragma unroll
    for (int r = 0; r < 8; r++)
#pragma unroll
        for (int c = 0; c < 4; c++) acc[r][c] = 0ull;

    for (int kc = 0; kc < 8; kc++) {
        int k0 = kc * 32;
        __syncthreads();
        // A tile: 64 rows x 32 k, stored transposed
#pragma unroll
        for (int i = 0; i < 2; i++) {
            int idx = tid + i * 256;
            int row = idx >> 3, kq = idx & 7;
            int node = row0 + row;
            int k = k0 + kq * 4;
            float4 v = make_float4(0.f, 0.f, 0.f, 0.f);
            if (node < NN) {
                if (k < IND) {
                    v = *(const float4*)(feat + (size_t)node * IND + k);
                } else {
                    v = *(const float4*)(g_agg + (size_t)node * IND + (k - IND));
                    float s0 = invd[row];
                    v.x *= s0; v.y *= s0; v.z *= s0; v.w *= s0;
                }
            }
            As[kq * 4 + 0][row] = v.x;
            As[kq * 4 + 1][row] = v.y;
            As[kq * 4 + 2][row] = v.z;
            As[kq * 4 + 3][row] = v.w;
        }
        // W tile: 32 k x 256 cols
#pragma unroll
        for (int i = 0; i < 8; i++) {
            int idx = tid + i * 256;
            int kk = idx >> 6, c4 = idx & 63;
            int k = k0 + kk;
            const float* w = (k < IND) ? (W_self + (size_t)k * HID + c4 * 4)
                                       : (W_neigh + (size_t)(k - IND) * HID + c4 * 4);
            *(float4*)&Ws[kk][c4 * 4] = *(const float4*)w;
        }
        __syncthreads();
#pragma unroll 8
        for (int kk = 0; kk < 32; kk++) {
            float4 a0 = *(const float4*)&As[kk][ty * 8];
            float4 a1 = *(const float4*)&As[kk][ty * 8 + 4];
            float4 w0 = *(const float4*)&Ws[kk][tx * 8];
            float4 w1 = *(const float4*)&Ws[kk][tx * 8 + 4];
            unsigned long long wp0 = pack2(w0.x, w0.y);
            unsigned long long wp1 = pack2(w0.z, w0.w);
            unsigned long long wp2 = pack2(w1.x, w1.y);
            unsigned long long wp3 = pack2(w1.z, w1.w);
            float ar[8] = {a0.x, a0.y, a0.z, a0.w, a1.x, a1.y, a1.z, a1.w};
#pragma unroll
            for (int r = 0; r < 8; r++) {
                unsigned long long ad = pack2(ar[r], ar[r]);
                fma2(acc[r][0], ad, wp0);
                fma2(acc[r][1], ad, wp1);
                fma2(acc[r][2], ad, wp2);
                fma2(acc[r][3], ad, wp3);
            }
        }
    }
    __syncthreads();

    // epilogue: bias + relu into hv (kept in regs), BN stats, per-graph pooling
    float hv[8][8];
    float csum[8], csq[8];
#pragma unroll
    for (int j = 0; j < 8; j++) { csum[j] = 0.f; csq[j] = 0.f; }
#pragma unroll
    for (int r = 0; r < 8; r++) {
        int node = row0 + ty * 8 + r;
        bool valid = (node < NN);
#pragma unroll
        for (int c2 = 0; c2 < 4; c2++) {
            float2 v = unpack2(acc[r][c2]);
            float h0 = fmaxf(v.x + bsh[tx * 8 + c2 * 2], 0.f);
            float h1 = fmaxf(v.y + bsh[tx * 8 + c2 * 2 + 1], 0.f);
            hv[r][c2 * 2]     = valid ? h0 : 0.f;
            hv[r][c2 * 2 + 1] = valid ? h1 : 0.f;
        }
        if (valid) {
#pragma unroll
            for (int j = 0; j < 8; j++) {
                csum[j] += hv[r][j];
                csq[j]  += hv[r][j] * hv[r][j];
            }
        }
    }
    float* red = &Ws[0][0];
#pragma unroll
    for (int j = 0; j < 8; j++) red[ty * 264 + tx * 8 + j] = csum[j];
    __syncthreads();
    {
        float s = 0.f;
#pragma unroll
        for (int t = 0; t < 8; t++) s += red[t * 264 + tid];
        redF1(&g_bnstats[tid], s);
    }
    __syncthreads();
#pragma unroll
    for (int j = 0; j < 8; j++) red[ty * 264 + tx * 8 + j] = csq[j];
    __syncthreads();
    {
        float q = 0.f;
#pragma unroll
        for (int t = 0; t < 8; t++) q += red[t * 264 + tid];
        redF1(&g_bnstats[256 + tid], q);
    }

    // per-graph raw pooling: graph_id is sorted, so a block spans few graphs
    if (tid == 0) {
        int lo = gids[0], hi = lo;
#pragma unroll 1
        for (int i = 1; i < 64; i++)
            if (gids[i] >= 0) hi = gids[i];
        grange[0] = lo; grange[1] = hi;
    }
    __syncthreads();
    int glo = grange[0], ghi = grange[1];
#pragma unroll 1
    for (int g = glo; g <= ghi; g++) {
        float s[8];
#pragma unroll
        for (int j = 0; j < 8; j++) s[j] = 0.f;
#pragma unroll
        for (int r = 0; r < 8; r++) {
            if (gids[ty * 8 + r] == g) {
#pragma unroll
                for (int j = 0; j < 8; j++) s[j] += hv[r][j];
            }
        }
        __syncthreads();
#pragma unroll
        for (int j = 0; j < 8; j++) red[ty * 264 + tx * 8 + j] = s[j];
        __syncthreads();
        float t = 0.f;
#pragma unroll
        for (int q = 0; q < 8; q++) t += red[q * 264 + tid];
        redF1(&g_poolraw[g * HID + tid], t);
    }
}

// ---------------- K2b: fold BN stats into per-column scale/shift ----------------
__global__ void bn_scale_kernel(const float* __restrict__ gamma,
                                const float* __restrict__ beta) {
    int c = threadIdx.x;
    float mean = g_bnstats[c] * (1.0f / NN);
    float var  = g_bnstats[256 + c] * (1.0f / NN) - mean * mean;
    float sc = gamma[c] * rsqrtf(var + BN_EPS);
    g_bnstats[1536 + c] = sc;
    g_bnstats[1792 + c] = beta[c] - mean * sc;
}

// ---------------- K4: z1 = relu(pooled @ W_lp + b) + stats ----------------
__global__ __launch_bounds__(HID) void lp1_kernel(const float* __restrict__ W_lp,
                                                  const float* __restrict__ b_lp) {
    __shared__ float row[HID];
    int g = blockIdx.x, c = threadIdx.x;
    float cntf = (float)g_cnt[g];
    row[c] = fmaf(g_poolraw[g * HID + c], g_bnstats[1536 + c],
                  cntf * g_bnstats[1792 + c]);
    __syncthreads();
    float acc = b_lp[c];
#pragma unroll 8
    for (int k = 0; k < HID; k++) acc = fmaf(row[k], __ldg(&W_lp[k * HID + c]), acc);
    float r = fmaxf(acc, 0.f);
    g_z1[g * HID + c] = r;
    atomicAdd(&g_bnstats[512 + c], r);
    atomicAdd(&g_bnstats[768 + c], r * r);
}

// ---------------- K5: BN(z1) -> p, z2 = relu(p @ W_lp + b) + stats ----------------
__global__ __launch_bounds__(HID) void lp2_kernel(const float* __restrict__ W_lp,
                                                  const float* __restrict__ b_lp,
                                                  const float* __restrict__ gamma,
                                                  const float* __restrict__ beta,
                                                  float* __restrict__ out_p) {
    __shared__ float row[HID];
    int g = blockIdx.x, c = threadIdx.x;
    float r = g_z1[g * HID + c];
    float mean = g_bnstats[512 + c] * (1.f / GG);
    float var  = g_bnstats[768 + c] * (1.f / GG) - mean * mean;
    float p = (r - mean) * rsqrtf(var + BN_EPS) * gamma[c] + beta[c];
    out_p[g * HID + c] = p;
    row[c] = p;
    __syncthreads();
    float acc = b_lp[c];
#pragma unroll 8
    for (int k = 0; k < HID; k++) acc = fmaf(row[k], __ldg(&W_lp[k * HID + c]), acc);
    float r2 = fmaxf(acc, 0.f);
    g_z2[g * HID + c] = r2;
    atomicAdd(&g_bnstats[1024 + c], r2);
    atomicAdd(&g_bnstats[1280 + c], r2 * r2);
}

// ---------------- K6: BN(z2) + log_softmax ----------------
__global__ __launch_bounds__(HID) void lp3_kernel(const float* __restrict__ gamma,
                                                  const float* __restrict__ beta,
                                                  float* __restrict__ out) {
    __shared__ float buf[HID];
    int g = blockIdx.x, c = threadIdx.x;
    float r = g_z2[g * HID + c];
    float mean = g_bnstats[1024 + c] * (1.f / GG);
    float var  = g_bnstats[1280 + c] * (1.f / GG) - mean * mean;
    float o = (r - mean) * rsqrtf(var + BN_EPS) * gamma[c] + beta[c];
    buf[c] = o;
    __syncthreads();
    for (int s = 128; s > 0; s >>= 1) {
        if (c < s) buf[c] = fmaxf(buf[c], buf[c + s]);
        __syncthreads();
    }
    float m = buf[0];
    __syncthreads();
    float e = expf(o - m);
    buf[c] = e;
    __syncthreads();
    for (int s = 128; s > 0; s >>= 1) {
        if (c < s) buf[c] += buf[c + s];
        __syncthreads();
    }
    float lse = logf(buf[0]);
    out[g * HID + c] = o - m - lse;
}

// ---------------- launch ----------------
extern "C" void kernel_launch(void* const* d_in, const int* in_sizes, int n_in,
                              void* d_out, int out_size) {
    const float* feat       = (const float*)d_in[0];
    const float* W_self     = (const float*)d_in[1];
    const float* W_neigh    = (const float*)d_in[2];
    const float* b_conv     = (const float*)d_in[3];
    const float* gamma_conv = (const float*)d_in[4];
    const float* beta_conv  = (const float*)d_in[5];
    const float* W_lp       = (const float*)d_in[6];
    const float* b_lp       = (const float*)d_in[7];
    const float* gamma_lp   = (const float*)d_in[8];
    const float* beta_lp    = (const float*)d_in[9];
    const int*   src        = (const int*)d_in[10];
    const int*   dst        = (const int*)d_in[11];
    const int*   graph_id   = (const int*)d_in[12];
    float* out = (float*)d_out;

    float* out_p;
    if (out_size >= 2 * GG * HID) {
        out_p = out + GG * HID;
    } else {
        void* pp = nullptr;
        cudaGetSymbolAddress(&pp, g_p);
        out_p = (float*)pp;
    }

    zero_kernel<<<(NN + 255) / 256, 256>>>();
    count_kernel<<<128, 1024>>>(graph_id);
    deg_kernel<<<(EE + 255) / 256, 256>>>(dst);
    scan_kernel<<<1, SCAN_T>>>();
    fill_kernel<<<(EE + 255) / 256, 256>>>(src, dst);
    agg_kernel<<<(NN * 32 + 255) / 256, 256>>>(feat);
    conv_gemm_kernel<<<(NN + 63) / 64, 256>>>(feat, W_self, W_neigh, b_conv, graph_id);
    bn_scale_kernel<<<1, HID>>>(gamma_conv, beta_conv);
    lp1_kernel<<<GG, HID>>>(W_lp, b_lp);
    lp2_kernel<<<GG, HID>>>(W_lp, b_lp, gamma_lp, beta_lp, out_p);
    lp3_kernel<<<GG, HID>>>(gamma_lp, beta_lp, out);
}

// round 6
// speedup vs baseline: 1.4153x; 1.3076x over previous
#include <cuda_runtime.h>
#include <cstdint>

#define NN  100000
#define EE  1000000
#define IND 128
#define HID 256
#define GG  64
#define BN_EPS 1e-5f

#define SCAN_B 1024
#define SCAN_NBLK ((NN + SCAN_B - 1) / SCAN_B)   // 98

// ---------------- scratch (static device globals; no allocation) ----------------
__device__ float g_agg[NN * IND];            // neighbor feature sums (written once, no init)
__device__ int   g_deg[NN];
__device__ int   g_ptr[NN];                  // CSR exclusive prefix
__device__ int   g_cur[NN];                  // fill cursors
__device__ int   g_esrc[EE];                 // CSR src lists
__device__ int   g_bsum[SCAN_NBLK];          // scan block sums
__device__ int   g_boff[SCAN_NBLK];          // scan block offsets
__device__ float g_poolraw[GG * HID];        // per-graph sums of relu(conv), pre-BN
__device__ int   g_cnt[GG];
__device__ float g_bnstats[8 * HID];
__device__ float g_z1[GG * HID];
__device__ float g_z2[GG * HID];
__device__ float g_p[GG * HID];

// ---------------- helpers ----------------
__device__ __forceinline__ unsigned long long pack2(float lo, float hi) {
    unsigned long long r;
    asm("mov.b64 %0, {%1, %2};" : "=l"(r) : "f"(lo), "f"(hi));
    return r;
}
__device__ __forceinline__ float2 unpack2(unsigned long long v) {
    float2 f;
    asm("mov.b64 {%0, %1}, %2;" : "=f"(f.x), "=f"(f.y) : "l"(v));
    return f;
}
__device__ __forceinline__ void fma2(unsigned long long& acc, unsigned long long a,
                                     unsigned long long b) {
    asm("fma.rn.f32x2 %0, %1, %2, %0;" : "+l"(acc) : "l"(a), "l"(b));
}
__device__ __forceinline__ void redF1(float* addr, float v) {
    asm volatile("red.global.add.f32 [%0], %1;" :: "l"(addr), "f"(v) : "memory");
}
__device__ __forceinline__ void redI1(int* addr, int v) {
    asm volatile("red.global.add.s32 [%0], %1;" :: "l"(addr), "r"(v) : "memory");
}

// ---------------- K0: zero small scratch ----------------
__global__ void zero_kernel() {
    int idx = blockIdx.x * blockDim.x + threadIdx.x;
    if (idx < NN) g_deg[idx] = 0;
    if (idx < GG * HID) g_poolraw[idx] = 0.f;
    if (idx < GG) g_cnt[idx] = 0;
    if (idx < 6 * HID) g_bnstats[idx] = 0.f;
}

// ---------------- K0b: per-graph node counts ----------------
__global__ void count_kernel(const int* __restrict__ graph_id) {
    __shared__ int cnt[GG];
    int t = threadIdx.x;
    if (t < GG) cnt[t] = 0;
    __syncthreads();
    for (int i = blockIdx.x * blockDim.x + t; i < NN; i += gridDim.x * blockDim.x)
        atomicAdd(&cnt[__ldg(&graph_id[i])], 1);
    __syncthreads();
    if (t < GG && cnt[t]) atomicAdd(&g_cnt[t], cnt[t]);
}

// ---------------- CSR phase 1: degree count ----------------
__global__ void deg_kernel(const int* __restrict__ dst) {
    int e = blockIdx.x * blockDim.x + threadIdx.x;
    if (e < EE) redI1(&g_deg[__ldg(&dst[e])], 1);
}

// ---------------- CSR phase 2a: per-block degree sums ----------------
__global__ __launch_bounds__(SCAN_B) void scan1_kernel() {
    __shared__ int sh[SCAN_B];
    int t = threadIdx.x;
    int i = blockIdx.x * SCAN_B + t;
    sh[t] = (i < NN) ? g_deg[i] : 0;
    __syncthreads();
#pragma unroll
    for (int s = SCAN_B / 2; s > 0; s >>= 1) {
        if (t < s) sh[t] += sh[t + s];
        __syncthreads();
    }
    if (t == 0) g_bsum[blockIdx.x] = sh[0];
}

// ---------------- CSR phase 2b: exclusive scan of block sums (tiny) ----------------
__global__ __launch_bounds__(128) void scan2_kernel() {
    __shared__ int sh[128];
    int t = threadIdx.x;
    int v = (t < SCAN_NBLK) ? g_bsum[t] : 0;
    sh[t] = v;
    __syncthreads();
#pragma unroll
    for (int off = 1; off < 128; off <<= 1) {
        int x = (t >= off) ? sh[t - off] : 0;
        __syncthreads();
        sh[t] += x;
        __syncthreads();
    }
    if (t < SCAN_NBLK) g_boff[t] = sh[t] - v;   // exclusive
}

// ---------------- CSR phase 2c: block-local exclusive scan + offset ----------------
__global__ __launch_bounds__(SCAN_B) void scan3_kernel() {
    __shared__ int sh[SCAN_B];
    int t = threadIdx.x;
    int i = blockIdx.x * SCAN_B + t;
    int v = (i < NN) ? g_deg[i] : 0;
    sh[t] = v;
    __syncthreads();
#pragma unroll
    for (int off = 1; off < SCAN_B; off <<= 1) {
        int x = (t >= off) ? sh[t - off] : 0;
        __syncthreads();
        sh[t] += x;
        __syncthreads();
    }
    if (i < NN) {
        int pos = g_boff[blockIdx.x] + sh[t] - v;   // exclusive
        g_ptr[i] = pos;
        g_cur[i] = pos;
    }
}

// ---------------- CSR phase 3: fill ----------------
__global__ void fill_kernel(const int* __restrict__ src,
                            const int* __restrict__ dst) {
    int e = blockIdx.x * blockDim.x + threadIdx.x;
    if (e >= EE) return;
    int d = __ldg(&dst[e]);
    int pos = atomicAdd(&g_cur[d], 1);
    g_esrc[pos] = __ldg(&src[e]);
}

// ---------------- K1: gather-aggregate (warp per node, no atomics) ----------------
__global__ __launch_bounds__(256) void agg_kernel(const float* __restrict__ feat) {
    int t = blockIdx.x * blockDim.x + threadIdx.x;
    int node = t >> 5;
    if (node >= NN) return;
    int lane = t & 31;
    int beg = __ldg(&g_ptr[node]);
    int d = __ldg(&g_deg[node]);
    float4 acc = make_float4(0.f, 0.f, 0.f, 0.f);
    for (int i = 0; i < d; i++) {
        int s = __ldg(&g_esrc[beg + i]);
        float4 v = __ldg(((const float4*)(feat + (size_t)s * IND)) + lane);
        acc.x += v.x; acc.y += v.y; acc.z += v.z; acc.w += v.w;
    }
    ((float4*)(g_agg + (size_t)node * IND))[lane] = acc;
}

// ---------------- K2: fused GEMM  h = relu([feat | agg/deg] @ [Wself;Wneigh] + b)
//                 + BN column statistics + per-graph raw pooling ----------------
__global__ __launch_bounds__(256, 2) void conv_gemm_kernel(
    const float* __restrict__ feat, const float* __restrict__ W_self,
    const float* __restrict__ W_neigh, const float* __restrict__ b_conv,
    const int* __restrict__ graph_id) {
    __shared__ float As[32][72];    // A tile, transposed [k][row], padded
    __shared__ float Ws[32][256];   // W tile [k][col]  (reused for reductions)
    __shared__ float invd[64];
    __shared__ float bsh[256];
    __shared__ int   gids[64];
    __shared__ int   grange[2];

    int tid = threadIdx.x;
    int row0 = blockIdx.x * 64;
    bsh[tid] = b_conv[tid];
    if (tid < 64) {
        int node = row0 + tid;
        float dg = 1.f;
        int gid = -1;
        if (node < NN) {
            dg = fmaxf((float)g_deg[node], 1.f);
            gid = __ldg(&graph_id[node]);
        }
        invd[tid] = 1.f / dg;
        gids[tid] = gid;
    }
    int ty = tid >> 5;   // row group (8)
    int tx = tid & 31;   // col group (32)

    unsigned long long acc[8][4];
#pragma unroll
    for (int r = 0; r < 8; r++)
#pragma unroll
        for (int c = 0; c < 4; c++) acc[r][c] = 0ull;

    for (int kc = 0; kc < 8; kc++) {
        int k0 = kc * 32;
        __syncthreads();
        // A tile: 64 rows x 32 k, stored transposed
#pragma unroll
        for (int i = 0; i < 2; i++) {
            int idx = tid + i * 256;
            int row = idx >> 3, kq = idx & 7;
            int node = row0 + row;
            int k = k0 + kq * 4;
            float4 v = make_float4(0.f, 0.f, 0.f, 0.f);
            if (node < NN) {
                if (k < IND) {
                    v = *(const float4*)(feat + (size_t)node * IND + k);
                } else {
                    v = *(const float4*)(g_agg + (size_t)node * IND + (k - IND));
                    float s0 = invd[row];
                    v.x *= s0; v.y *= s0; v.z *= s0; v.w *= s0;
                }
            }
            As[kq * 4 + 0][row] = v.x;
            As[kq * 4 + 1][row] = v.y;
            As[kq * 4 + 2][row] = v.z;
            As[kq * 4 + 3][row] = v.w;
        }
        // W tile: 32 k x 256 cols
#pragma unroll
        for (int i = 0; i < 8; i++) {
            int idx = tid + i * 256;
            int kk = idx >> 6, c4 = idx & 63;
            int k = k0 + kk;
            const float* w = (k < IND) ? (W_self + (size_t)k * HID + c4 * 4)
                                       : (W_neigh + (size_t)(k - IND) * HID + c4 * 4);
            *(float4*)&Ws[kk][c4 * 4] = *(const float4*)w;
        }
        __syncthreads();
#pragma unroll 8
        for (int kk = 0; kk < 32; kk++) {
            float4 a0 = *(const float4*)&As[kk][ty * 8];
            float4 a1 = *(const float4*)&As[kk][ty * 8 + 4];
            float4 w0 = *(const float4*)&Ws[kk][tx * 8];
            float4 w1 = *(const float4*)&Ws[kk][tx * 8 + 4];
            unsigned long long wp0 = pack2(w0.x, w0.y);
            unsigned long long wp1 = pack2(w0.z, w0.w);
            unsigned long long wp2 = pack2(w1.x, w1.y);
            unsigned long long wp3 = pack2(w1.z, w1.w);
            float ar[8] = {a0.x, a0.y, a0.z, a0.w, a1.x, a1.y, a1.z, a1.w};
#pragma unroll
            for (int r = 0; r < 8; r++) {
                unsigned long long ad = pack2(ar[r], ar[r]);
                fma2(acc[r][0], ad, wp0);
                fma2(acc[r][1], ad, wp1);
                fma2(acc[r][2], ad, wp2);
                fma2(acc[r][3], ad, wp3);
            }
        }
    }
    __syncthreads();

    // epilogue: bias + relu into hv (kept in regs), BN stats, per-graph pooling
    float hv[8][8];
    float csum[8], csq[8];
#pragma unroll
    for (int j = 0; j < 8; j++) { csum[j] = 0.f; csq[j] = 0.f; }
#pragma unroll
    for (int r = 0; r < 8; r++) {
        int node = row0 + ty * 8 + r;
        bool valid = (node < NN);
#pragma unroll
        for (int c2 = 0; c2 < 4; c2++) {
            float2 v = unpack2(acc[r][c2]);
            float h0 = fmaxf(v.x + bsh[tx * 8 + c2 * 2], 0.f);
            float h1 = fmaxf(v.y + bsh[tx * 8 + c2 * 2 + 1], 0.f);
            hv[r][c2 * 2]     = valid ? h0 : 0.f;
            hv[r][c2 * 2 + 1] = valid ? h1 : 0.f;
        }
        if (valid) {
#pragma unroll
            for (int j = 0; j < 8; j++) {
                csum[j] += hv[r][j];
                csq[j]  += hv[r][j] * hv[r][j];
            }
        }
    }
    float* red = &Ws[0][0];
#pragma unroll
    for (int j = 0; j < 8; j++) red[ty * 264 + tx * 8 + j] = csum[j];
    __syncthreads();
    {
        float s = 0.f;
#pragma unroll
        for (int t = 0; t < 8; t++) s += red[t * 264 + tid];
        redF1(&g_bnstats[tid], s);
    }
    __syncthreads();
#pragma unroll
    for (int j = 0; j < 8; j++) red[ty * 264 + tx * 8 + j] = csq[j];
    __syncthreads();
    {
        float q = 0.f;
#pragma unroll
        for (int t = 0; t < 8; t++) q += red[t * 264 + tid];
        redF1(&g_bnstats[256 + tid], q);
    }

    // per-graph raw pooling: graph_id is sorted, so a block spans few graphs
    if (tid == 0) {
        int lo = gids[0], hi = lo;
#pragma unroll 1
        for (int i = 1; i < 64; i++)
            if (gids[i] >= 0) hi = gids[i];
        grange[0] = lo; grange[1] = hi;
    }
    __syncthreads();
    int glo = grange[0], ghi = grange[1];
#pragma unroll 1
    for (int g = glo; g <= ghi; g++) {
        float s[8];
#pragma unroll
        for (int j = 0; j < 8; j++) s[j] = 0.f;
#pragma unroll
        for (int r = 0; r < 8; r++) {
            if (gids[ty * 8 + r] == g) {
#pragma unroll
                for (int j = 0; j < 8; j++) s[j] += hv[r][j];
            }
        }
        __syncthreads();
#pragma unroll
        for (int j = 0; j < 8; j++) red[ty * 264 + tx * 8 + j] = s[j];
        __syncthreads();
        float t = 0.f;
#pragma unroll
        for (int q = 0; q < 8; q++) t += red[q * 264 + tid];
        redF1(&g_poolraw[g * HID + tid], t);
    }
}

// ---------------- K2b: fold BN stats into per-column scale/shift ----------------
__global__ void bn_scale_kernel(const float* __restrict__ gamma,
                                const float* __restrict__ beta) {
    int c = threadIdx.x;
    float mean = g_bnstats[c] * (1.0f / NN);
    float var  = g_bnstats[256 + c] * (1.0f / NN) - mean * mean;
    float sc = gamma[c] * rsqrtf(var + BN_EPS);
    g_bnstats[1536 + c] = sc;
    g_bnstats[1792 + c] = beta[c] - mean * sc;
}

// ---------------- K4: z1 = relu(pooled @ W_lp + b) + stats ----------------
__global__ __launch_bounds__(HID) void lp1_kernel(const float* __restrict__ W_lp,
                                                  const float* __restrict__ b_lp) {
    __shared__ float row[HID];
    int g = blockIdx.x, c = threadIdx.x;
    float cntf = (float)g_cnt[g];
    row[c] = fmaf(g_poolraw[g * HID + c], g_bnstats[1536 + c],
                  cntf * g_bnstats[1792 + c]);
    __syncthreads();
    float acc = b_lp[c];
#pragma unroll 8
    for (int k = 0; k < HID; k++) acc = fmaf(row[k], __ldg(&W_lp[k * HID + c]), acc);
    float r = fmaxf(acc, 0.f);
    g_z1[g * HID + c] = r;
    atomicAdd(&g_bnstats[512 + c], r);
    atomicAdd(&g_bnstats[768 + c], r * r);
}

// ---------------- K5: BN(z1) -> p, z2 = relu(p @ W_lp + b) + stats ----------------
__global__ __launch_bounds__(HID) void lp2_kernel(const float* __restrict__ W_lp,
                                                  const float* __restrict__ b_lp,
                                                  const float* __restrict__ gamma,
                                                  const float* __restrict__ beta,
                                                  float* __restrict__ out_p) {
    __shared__ float row[HID];
    int g = blockIdx.x, c = threadIdx.x;
    float r = g_z1[g * HID + c];
    float mean = g_bnstats[512 + c] * (1.f / GG);
    float var  = g_bnstats[768 + c] * (1.f / GG) - mean * mean;
    float p = (r - mean) * rsqrtf(var + BN_EPS) * gamma[c] + beta[c];
    out_p[g * HID + c] = p;
    row[c] = p;
    __syncthreads();
    float acc = b_lp[c];
#pragma unroll 8
    for (int k = 0; k < HID; k++) acc = fmaf(row[k], __ldg(&W_lp[k * HID + c]), acc);
    float r2 = fmaxf(acc, 0.f);
    g_z2[g * HID + c] = r2;
    atomicAdd(&g_bnstats[1024 + c], r2);
    atomicAdd(&g_bnstats[1280 + c], r2 * r2);
}

// ---------------- K6: BN(z2) + log_softmax ----------------
__global__ __launch_bounds__(HID) void lp3_kernel(const float* __restrict__ gamma,
                                                  const float* __restrict__ beta,
                                                  float* __restrict__ out) {
    __shared__ float buf[HID];
    int g = blockIdx.x, c = threadIdx.x;
    float r = g_z2[g * HID + c];
    float mean = g_bnstats[1024 + c] * (1.f / GG);
    float var  = g_bnstats[1280 + c] * (1.f / GG) - mean * mean;
    float o = (r - mean) * rsqrtf(var + BN_EPS) * gamma[c] + beta[c];
    buf[c] = o;
    __syncthreads();
    for (int s = 128; s > 0; s >>= 1) {
        if (c < s) buf[c] = fmaxf(buf[c], buf[c + s]);
        __syncthreads();
    }
    float m = buf[0];
    __syncthreads();
    float e = expf(o - m);
    buf[c] = e;
    __syncthreads();
    for (int s = 128; s > 0; s >>= 1) {
        if (c < s) buf[c] += buf[c + s];
        __syncthreads();
    }
    float lse = logf(buf[0]);
    out[g * HID + c] = o - m - lse;
}

// ---------------- launch ----------------
extern "C" void kernel_launch(void* const* d_in, const int* in_sizes, int n_in,
                              void* d_out, int out_size) {
    const float* feat       = (const float*)d_in[0];
    const float* W_self     = (const float*)d_in[1];
    const float* W_neigh    = (const float*)d_in[2];
    const float* b_conv     = (const float*)d_in[3];
    const float* gamma_conv = (const float*)d_in[4];
    const float* beta_conv  = (const float*)d_in[5];
    const float* W_lp       = (const float*)d_in[6];
    const float* b_lp       = (const float*)d_in[7];
    const float* gamma_lp   = (const float*)d_in[8];
    const float* beta_lp    = (const float*)d_in[9];
    const int*   src        = (const int*)d_in[10];
    const int*   dst        = (const int*)d_in[11];
    const int*   graph_id   = (const int*)d_in[12];
    float* out = (float*)d_out;

    float* out_p;
    if (out_size >= 2 * GG * HID) {
        out_p = out + GG * HID;
    } else {
        void* pp = nullptr;
        cudaGetSymbolAddress(&pp, g_p);
        out_p = (float*)pp;
    }

    zero_kernel<<<(NN + 255) / 256, 256>>>();
    count_kernel<<<128, 1024>>>(graph_id);
    deg_kernel<<<(EE + 255) / 256, 256>>>(dst);
    scan1_kernel<<<SCAN_NBLK, SCAN_B>>>();
    scan2_kernel<<<1, 128>>>();
    scan3_kernel<<<SCAN_NBLK, SCAN_B>>>();
    fill_kernel<<<(EE + 255) / 256, 256>>>(src, dst);
    agg_kernel<<<(NN * 32 + 255) / 256, 256>>>(feat);
    conv_gemm_kernel<<<(NN + 63) / 64, 256>>>(feat, W_self, W_neigh, b_conv, graph_id);
    bn_scale_kernel<<<1, HID>>>(gamma_conv, beta_conv);
    lp1_kernel<<<GG, HID>>>(W_lp, b_lp);
    lp2_kernel<<<GG, HID>>>(W_lp, b_lp, gamma_lp, beta_lp, out_p);
    lp3_kernel<<<GG, HID>>>(gamma_lp, beta_lp, out);
}

// round 7
// speedup vs baseline: 2.2722x; 1.6055x over previous
#include <cuda_runtime.h>
#include <cuda_bf16.h>
#include <cstdint>

#define NN  100000
#define EE  1000000
#define IND 128
#define HID 256
#define GG  64
#define BN_EPS 1e-5f

#define SCAN_B 1024
#define SCAN_NBLK ((NN + SCAN_B - 1) / SCAN_B)   // 98

#define TILE_M 64
#define MBLK ((NN + TILE_M - 1) / TILE_M)        // 1563

// ---------------- scratch (static device globals; no allocation) ----------------
__device__ float g_agg[NN * IND];
__device__ int   g_deg[NN];
__device__ int   g_ptr[NN];
__device__ int   g_cur[NN];
__device__ int   g_esrc[EE];
__device__ int   g_bsum[SCAN_NBLK];
__device__ int   g_boff[SCAN_NBLK];
__device__ float g_poolraw[GG * HID];
__device__ int   g_cnt[GG];
__device__ float g_bnstats[8 * HID];
__device__ float g_z1[GG * HID];
__device__ float g_z2[GG * HID];
__device__ float g_p[GG * HID];
// bf16 W images, row-major [K=256][N=256]
__device__ __nv_bfloat16 g_Bhi[256 * 256];
__device__ __nv_bfloat16 g_Blo[256 * 256];

// ---------------- helpers ----------------
__device__ __forceinline__ void redF1(float* addr, float v) {
    asm volatile("red.global.add.f32 [%0], %1;" :: "l"(addr), "f"(v) : "memory");
}
__device__ __forceinline__ void redI1(int* addr, int v) {
    asm volatile("red.global.add.s32 [%0], %1;" :: "l"(addr), "r"(v) : "memory");
}
__device__ __forceinline__ uint32_t bfu(__nv_bfloat16 h) {
    return (uint32_t)__bfloat16_as_ushort(h);
}
__device__ __forceinline__ uint32_t smem_u32(const void* p) {
    uint32_t a;
    asm("{ .reg .u64 t; cvta.to.shared.u64 t, %1; cvt.u32.u64 %0, t; }"
        : "=r"(a) : "l"(p));
    return a;
}
__device__ __forceinline__ void ldsm4(uint32_t* r, uint32_t a) {
    asm volatile("ldmatrix.sync.aligned.m8n8.x4.shared.b16 {%0,%1,%2,%3}, [%4];"
        : "=r"(r[0]), "=r"(r[1]), "=r"(r[2]), "=r"(r[3]) : "r"(a));
}
__device__ __forceinline__ void ldsm4t(uint32_t* r, uint32_t a) {
    asm volatile("ldmatrix.sync.aligned.m8n8.x4.trans.shared.b16 {%0,%1,%2,%3}, [%4];"
        : "=r"(r[0]), "=r"(r[1]), "=r"(r[2]), "=r"(r[3]) : "r"(a));
}
__device__ __forceinline__ void mma16816(float* d, const uint32_t* a, const uint32_t* b) {
    asm volatile("mma.sync.aligned.m16n8k16.row.col.f32.bf16.bf16.f32 "
        "{%0,%1,%2,%3}, {%4,%5,%6,%7}, {%8,%9}, {%0,%1,%2,%3};"
        : "+f"(d[0]), "+f"(d[1]), "+f"(d[2]), "+f"(d[3])
        : "r"(a[0]), "r"(a[1]), "r"(a[2]), "r"(a[3]), "r"(b[0]), "r"(b[1]));
}

// ---------------- K0: zero small scratch ----------------
__global__ void zero_kernel() {
    int idx = blockIdx.x * blockDim.x + threadIdx.x;
    if (idx < NN) g_deg[idx] = 0;
    if (idx < GG * HID) g_poolraw[idx] = 0.f;
    if (idx < GG) g_cnt[idx] = 0;
    if (idx < 6 * HID) g_bnstats[idx] = 0.f;
}

// ---------------- K0b: per-graph node counts ----------------
__global__ void count_kernel(const int* __restrict__ graph_id) {
    __shared__ int cnt[GG];
    int t = threadIdx.x;
    if (t < GG) cnt[t] = 0;
    __syncthreads();
    for (int i = blockIdx.x * blockDim.x + t; i < NN; i += gridDim.x * blockDim.x)
        atomicAdd(&cnt[__ldg(&graph_id[i])], 1);
    __syncthreads();
    if (t < GG && cnt[t]) atomicAdd(&g_cnt[t], cnt[t]);
}

// ---------------- CSR phases ----------------
__global__ void deg_kernel(const int* __restrict__ dst) {
    int e = blockIdx.x * blockDim.x + threadIdx.x;
    if (e < EE) redI1(&g_deg[__ldg(&dst[e])], 1);
}

__global__ __launch_bounds__(SCAN_B) void scan1_kernel() {
    __shared__ int sh[SCAN_B];
    int t = threadIdx.x;
    int i = blockIdx.x * SCAN_B + t;
    sh[t] = (i < NN) ? g_deg[i] : 0;
    __syncthreads();
#pragma unroll
    for (int s = SCAN_B / 2; s > 0; s >>= 1) {
        if (t < s) sh[t] += sh[t + s];
        __syncthreads();
    }
    if (t == 0) g_bsum[blockIdx.x] = sh[0];
}

__global__ __launch_bounds__(128) void scan2_kernel() {
    __shared__ int sh[128];
    int t = threadIdx.x;
    int v = (t < SCAN_NBLK) ? g_bsum[t] : 0;
    sh[t] = v;
    __syncthreads();
#pragma unroll
    for (int off = 1; off < 128; off <<= 1) {
        int x = (t >= off) ? sh[t - off] : 0;
        __syncthreads();
        sh[t] += x;
        __syncthreads();
    }
    if (t < SCAN_NBLK) g_boff[t] = sh[t] - v;
}

__global__ __launch_bounds__(SCAN_B) void scan3_kernel() {
    __shared__ int sh[SCAN_B];
    int t = threadIdx.x;
    int i = blockIdx.x * SCAN_B + t;
    int v = (i < NN) ? g_deg[i] : 0;
    sh[t] = v;
    __syncthreads();
#pragma unroll
    for (int off = 1; off < SCAN_B; off <<= 1) {
        int x = (t >= off) ? sh[t - off] : 0;
        __syncthreads();
        sh[t] += x;
        __syncthreads();
    }
    if (i < NN) {
        int pos = g_boff[blockIdx.x] + sh[t] - v;
        g_ptr[i] = pos;
        g_cur[i] = pos;
    }
}

__global__ void fill_kernel(const int* __restrict__ src,
                            const int* __restrict__ dst) {
    int e = blockIdx.x * blockDim.x + threadIdx.x;
    if (e >= EE) return;
    int d = __ldg(&dst[e]);
    int pos = atomicAdd(&g_cur[d], 1);
    g_esrc[pos] = __ldg(&src[e]);
}

// ---------------- K1: gather-aggregate (warp per node, no atomics) ----------------
__global__ __launch_bounds__(256) void agg_kernel(const float* __restrict__ feat) {
    int t = blockIdx.x * blockDim.x + threadIdx.x;
    int node = t >> 5;
    if (node >= NN) return;
    int lane = t & 31;
    int beg = __ldg(&g_ptr[node]);
    int d = __ldg(&g_deg[node]);
    float4 acc = make_float4(0.f, 0.f, 0.f, 0.f);
    for (int i = 0; i < d; i++) {
        int s = __ldg(&g_esrc[beg + i]);
        float4 v = __ldg(((const float4*)(feat + (size_t)s * IND)) + lane);
        acc.x += v.x; acc.y += v.y; acc.z += v.z; acc.w += v.w;
    }
    ((float4*)(g_agg + (size_t)node * IND))[lane] = acc;
}

// ---------------- Kw: W -> bf16 hi/lo row-major images ----------------
__global__ void wprep_kernel(const float* __restrict__ W_self,
                             const float* __restrict__ W_neigh) {
    int k = blockIdx.x;
    int n = threadIdx.x;
    float w = (k < IND) ? W_self[k * HID + n] : W_neigh[(k - IND) * HID + n];
    __nv_bfloat16 hi = __float2bfloat16(w);
    __nv_bfloat16 lo = __float2bfloat16(w - __bfloat162float(hi));
    g_Bhi[k * 256 + n] = hi;
    g_Blo[k * 256 + n] = lo;
}

// ---------------- K2: mma.sync split-bf16 GEMM + relu + BN stats + pooling ------
// smem stage: Ah [64][40]h @0 (5120), Al @5120, Bh [32][136]h @10240 (8704),
//             Bl @18944; stage size 27648, double buffered.
// C f32[64][132] aliases stage smem after mainloop.
#define ST_SZ    27648
#define AOF_LO   5120
#define OFF_BH   10240
#define BOF_LO   8704
#define OFF_BSH  55296
#define OFF_INVD 55808
#define OFF_GIDS 56064
#define OFF_GRNG 56320
#define OFF_RS   56336
#define OFF_RQ   57360
#define DYN_SMEM 58384

__global__ __launch_bounds__(256) void conv_mma_kernel(
    const float* __restrict__ feat, const float* __restrict__ b_conv,
    const int* __restrict__ graph_id) {
    extern __shared__ char p0[];
    uint32_t sm = smem_u32(p0);
    float* s_bsh  = (float*)(p0 + OFF_BSH);
    float* s_invd = (float*)(p0 + OFF_INVD);
    int*   s_gids = (int*)(p0 + OFF_GIDS);
    int*   s_grng = (int*)(p0 + OFF_GRNG);
    float* s_rs   = (float*)(p0 + OFF_RS);
    float* s_rq   = (float*)(p0 + OFF_RQ);

    int tid = threadIdx.x;
    int wid = tid >> 5;
    int lane = tid & 31;
    int row0 = blockIdx.x * TILE_M;
    int n0 = blockIdx.y * 128;

    if (tid < 128) s_bsh[tid] = b_conv[n0 + tid];
    if (tid < TILE_M) {
        int node = row0 + tid;
        float dg = 1.f;
        int gid = -1;
        if (node < NN) {
            dg = fmaxf((float)g_deg[node], 1.f);
            gid = __ldg(&graph_id[node]);
        }
        s_invd[tid] = 1.f / dg;
        s_gids[tid] = gid;
    }
    __syncthreads();
    if (tid == 0) {
        int lo = s_gids[0], hi = lo;
#pragma unroll 1
        for (int i = 1; i < TILE_M; i++)
            if (s_gids[i] >= 0) hi = s_gids[i];
        s_grng[0] = lo; s_grng[1] = hi;
    }

    int wm = (wid >> 2) * 32;    // warp M offset (0/32)
    int wn = (wid & 3) * 32;     // warp N offset (0/32/64/96)

    float acc[2][4][4];
#pragma unroll
    for (int m = 0; m < 2; m++)
#pragma unroll
        for (int j = 0; j < 4; j++)
#pragma unroll
            for (int d = 0; d < 4; d++) acc[m][j][d] = 0.f;

    // per-lane ldmatrix base addresses
    uint32_t Abase = sm + (wm + (lane & 15)) * 80 + (lane >> 4) * 16;
    uint32_t Bbase = sm + OFF_BH + (lane & 15) * 272 + (wn + (lane >> 4) * 8) * 2;

    // prefetch regs
    float4 pa[2];
    uint4 pbh[2], pbl[2];

    auto load_g = [&](int kc) {
#pragma unroll
        for (int it = 0; it < 2; it++) {
            int e = tid + it * 256;
            int r = e >> 3, k4 = e & 7;
            int node = row0 + r;
            float4 v = make_float4(0.f, 0.f, 0.f, 0.f);
            if (node < NN) {
                if (kc < 4)
                    v = __ldg((const float4*)(feat + (size_t)node * IND + kc * 32 + k4 * 4));
                else
                    v = *(const float4*)(g_agg + (size_t)node * IND + (kc - 4) * 32 + k4 * 4);
            }
            pa[it] = v;
        }
#pragma unroll
        for (int it = 0; it < 2; it++) {
            int e = tid + it * 256;
            int kk = e >> 4, c = e & 15;
            int krow = kc * 32 + kk;
            pbh[it] = *(const uint4*)(g_Bhi + (size_t)krow * 256 + n0 + c * 8);
            pbl[it] = *(const uint4*)(g_Blo + (size_t)krow * 256 + n0 + c * 8);
        }
    };
    auto store_s = [&](int buf, int kc) {
        char* st = p0 + buf * ST_SZ;
        bool isagg = (kc >= 4);
#pragma unroll
        for (int it = 0; it < 2; it++) {
            int e = tid + it * 256;
            int r = e >> 3, k4 = e & 7;
            float4 v = pa[it];
            if (isagg) {
                float s = s_invd[r];
                v.x *= s; v.y *= s; v.z *= s; v.w *= s;
            }
            __nv_bfloat16 h0 = __float2bfloat16(v.x);
            __nv_bfloat16 h1 = __float2bfloat16(v.y);
            __nv_bfloat16 h2 = __float2bfloat16(v.z);
            __nv_bfloat16 h3 = __float2bfloat16(v.w);
            __nv_bfloat16 l0 = __float2bfloat16(v.x - __bfloat162float(h0));
            __nv_bfloat16 l1 = __float2bfloat16(v.y - __bfloat162float(h1));
            __nv_bfloat16 l2 = __float2bfloat16(v.z - __bfloat162float(h2));
            __nv_bfloat16 l3 = __float2bfloat16(v.w - __bfloat162float(h3));
            uint2 hu = make_uint2((bfu(h1) << 16) | bfu(h0), (bfu(h3) << 16) | bfu(h2));
            uint2 lu = make_uint2((bfu(l1) << 16) | bfu(l0), (bfu(l3) << 16) | bfu(l2));
            *(uint2*)(st + r * 80 + k4 * 8) = hu;
            *(uint2*)(st + AOF_LO + r * 80 + k4 * 8) = lu;
        }
#pragma unroll
        for (int it = 0; it < 2; it++) {
            int e = tid + it * 256;
            int kk = e >> 4, c = e & 15;
            *(uint4*)(st + OFF_BH + kk * 272 + c * 16) = pbh[it];
            *(uint4*)(st + OFF_BH + BOF_LO + kk * 272 + c * 16) = pbl[it];
        }
    };
    auto compute = [&](int buf) {
        uint32_t so = buf * ST_SZ;
#pragma unroll
        for (int ks = 0; ks < 2; ks++) {
            uint32_t ab = Abase + so + ks * 32;
            uint32_t bb = Bbase + so + ks * 4352;   // ks*16*272
            uint32_t ah[2][4], al[2][4], bh[8], bl[8];
            ldsm4(ah[0], ab);
            ldsm4(ah[1], ab + 1280);                // +16 rows * 80
            ldsm4(al[0], ab + AOF_LO);
            ldsm4(al[1], ab + AOF_LO + 1280);
            ldsm4t(&bh[0], bb);
            ldsm4t(&bh[4], bb + 32);                // +16 cols * 2B
            ldsm4t(&bl[0], bb + BOF_LO);
            ldsm4t(&bl[4], bb + BOF_LO + 32);
#pragma unroll
            for (int m = 0; m < 2; m++)
#pragma unroll
                for (int j = 0; j < 4; j++) {
                    mma16816(acc[m][j], ah[m], &bh[2 * j]);
                    mma16816(acc[m][j], ah[m], &bl[2 * j]);
                    mma16816(acc[m][j], al[m], &bh[2 * j]);
                }
        }
    };

    // -------- main loop: 8 K-chunks of 32, double-buffered --------
    load_g(0);
    store_s(0, 0);
    __syncthreads();
#pragma unroll 1
    for (int kc = 0; kc < 8; kc++) {
        if (kc < 7) load_g(kc + 1);
        compute(kc & 1);
        if (kc < 7) store_s((kc + 1) & 1, kc + 1);
        __syncthreads();
    }

    // -------- epilogue: C to smem, bias+relu, BN stats, pooling --------
    float* C = (float*)p0;   // [64][132], aliases stage smem
#pragma unroll
    for (int m = 0; m < 2; m++)
#pragma unroll
        for (int j = 0; j < 4; j++) {
            int rr = wm + m * 16 + (lane >> 2);
            int cc = wn + j * 8 + (lane & 3) * 2;
            C[rr * 132 + cc]           = acc[m][j][0];
            C[rr * 132 + cc + 1]       = acc[m][j][1];
            C[(rr + 8) * 132 + cc]     = acc[m][j][2];
            C[(rr + 8) * 132 + cc + 1] = acc[m][j][3];
        }
    __syncthreads();

    int col = tid & 127, q = tid >> 7;   // half of rows (32 each)
    {
        float b = s_bsh[col];
        float sum = 0.f, sq = 0.f;
#pragma unroll 8
        for (int rr = q * 32; rr < q * 32 + 32; rr++) {
            float v = C[rr * 132 + col] + b;
            v = (s_gids[rr] >= 0) ? fmaxf(v, 0.f) : 0.f;
            C[rr * 132 + col] = v;
            sum += v; sq += v * v;
        }
        s_rs[q * 128 + col] = sum;
        s_rq[q * 128 + col] = sq;
    }
    __syncthreads();
    if (tid < 128) {
        redF1(&g_bnstats[n0 + tid], s_rs[tid] + s_rs[128 + tid]);
    } else {
        int c2 = tid - 128;
        redF1(&g_bnstats[256 + n0 + c2], s_rq[c2] + s_rq[128 + c2]);
    }
    int glo = s_grng[0], ghi = s_grng[1];
#pragma unroll 1
    for (int g = glo; g <= ghi; g++) {
        float pp = 0.f;
#pragma unroll 8
        for (int rr = q * 32; rr < q * 32 + 32; rr++)
            if (s_gids[rr] == g) pp += C[rr * 132 + col];
        __syncthreads();
        s_rs[q * 128 + col] = pp;
        __syncthreads();
        if (tid < 128)
            redF1(&g_poolraw[g * HID + n0 + tid], s_rs[tid] + s_rs[128 + tid]);
    }
}

// ---------------- K2b: fold BN stats into per-column scale/shift ----------------
__global__ void bn_scale_kernel(const float* __restrict__ gamma,
                                const float* __restrict__ beta) {
    int c = threadIdx.x;
    float mean = g_bnstats[c] * (1.0f / NN);
    float var  = g_bnstats[256 + c] * (1.0f / NN) - mean * mean;
    float sc = gamma[c] * rsqrtf(var + BN_EPS);
    g_bnstats[1536 + c] = sc;
    g_bnstats[1792 + c] = beta[c] - mean * sc;
}

// ---------------- K4: z1 = relu(pooled @ W_lp + b) + stats ----------------
__global__ __launch_bounds__(HID) void lp1_kernel(const float* __restrict__ W_lp,
                                                  const float* __restrict__ b_lp) {
    __shared__ float row[HID];
    int g = blockIdx.x, c = threadIdx.x;
    float cntf = (float)g_cnt[g];
    row[c] = fmaf(g_poolraw[g * HID + c], g_bnstats[1536 + c],
                  cntf * g_bnstats[1792 + c]);
    __syncthreads();
    float acc = b_lp[c];
#pragma unroll 8
    for (int k = 0; k < HID; k++) acc = fmaf(row[k], __ldg(&W_lp[k * HID + c]), acc);
    float r = fmaxf(acc, 0.f);
    g_z1[g * HID + c] = r;
    atomicAdd(&g_bnstats[512 + c], r);
    atomicAdd(&g_bnstats[768 + c], r * r);
}

// ---------------- K5: BN(z1) -> p, z2 = relu(p @ W_lp + b) + stats ----------------
__global__ __launch_bounds__(HID) void lp2_kernel(const float* __restrict__ W_lp,
                                                  const float* __restrict__ b_lp,
                                                  const float* __restrict__ gamma,
                                                  const float* __restrict__ beta,
                                                  float* __restrict__ out_p) {
    __shared__ float row[HID];
    int g = blockIdx.x, c = threadIdx.x;
    float r = g_z1[g * HID + c];
    float mean = g_bnstats[512 + c] * (1.f / GG);
    float var  = g_bnstats[768 + c] * (1.f / GG) - mean * mean;
    float p = (r - mean) * rsqrtf(var + BN_EPS) * gamma[c] + beta[c];
    out_p[g * HID + c] = p;
    row[c] = p;
    __syncthreads();
    float acc = b_lp[c];
#pragma unroll 8
    for (int k = 0; k < HID; k++) acc = fmaf(row[k], __ldg(&W_lp[k * HID + c]), acc);
    float r2 = fmaxf(acc, 0.f);
    g_z2[g * HID + c] = r2;
    atomicAdd(&g_bnstats[1024 + c], r2);
    atomicAdd(&g_bnstats[1280 + c], r2 * r2);
}

// ---------------- K6: BN(z2) + log_softmax ----------------
__global__ __launch_bounds__(HID) void lp3_kernel(const float* __restrict__ gamma,
                                                  const float* __restrict__ beta,
                                                  float* __restrict__ out) {
    __shared__ float buf[HID];
    int g = blockIdx.x, c = threadIdx.x;
    float r = g_z2[g * HID + c];
    float mean = g_bnstats[1024 + c] * (1.f / GG);
    float var  = g_bnstats[1280 + c] * (1.f / GG) - mean * mean;
    float o = (r - mean) * rsqrtf(var + BN_EPS) * gamma[c] + beta[c];
    buf[c] = o;
    __syncthreads();
    for (int s = 128; s > 0; s >>= 1) {
        if (c < s) buf[c] = fmaxf(buf[c], buf[c + s]);
        __syncthreads();
    }
    float m = buf[0];
    __syncthreads();
    float e = expf(o - m);
    buf[c] = e;
    __syncthreads();
    for (int s = 128; s > 0; s >>= 1) {
        if (c < s) buf[c] += buf[c + s];
        __syncthreads();
    }
    float lse = logf(buf[0]);
    out[g * HID + c] = o - m - lse;
}

// ---------------- launch ----------------
extern "C" void kernel_launch(void* const* d_in, const int* in_sizes, int n_in,
                              void* d_out, int out_size) {
    const float* feat       = (const float*)d_in[0];
    const float* W_self     = (const float*)d_in[1];
    const float* W_neigh    = (const float*)d_in[2];
    const float* b_conv     = (const float*)d_in[3];
    const float* gamma_conv = (const float*)d_in[4];
    const float* beta_conv  = (const float*)d_in[5];
    const float* W_lp       = (const float*)d_in[6];
    const float* b_lp       = (const float*)d_in[7];
    const float* gamma_lp   = (const float*)d_in[8];
    const float* beta_lp    = (const float*)d_in[9];
    const int*   src        = (const int*)d_in[10];
    const int*   dst        = (const int*)d_in[11];
    const int*   graph_id   = (const int*)d_in[12];
    float* out = (float*)d_out;

    float* out_p;
    if (out_size >= 2 * GG * HID) {
        out_p = out + GG * HID;
    } else {
        void* pp = nullptr;
        cudaGetSymbolAddress(&pp, g_p);
        out_p = (float*)pp;
    }

    cudaFuncSetAttribute(conv_mma_kernel,
                         cudaFuncAttributeMaxDynamicSharedMemorySize, DYN_SMEM);

    zero_kernel<<<(NN + 255) / 256, 256>>>();
    count_kernel<<<128, 1024>>>(graph_id);
    deg_kernel<<<(EE + 255) / 256, 256>>>(dst);
    scan1_kernel<<<SCAN_NBLK, SCAN_B>>>();
    scan2_kernel<<<1, 128>>>();
    scan3_kernel<<<SCAN_NBLK, SCAN_B>>>();
    fill_kernel<<<(EE + 255) / 256, 256>>>(src, dst);
    wprep_kernel<<<256, 256>>>(W_self, W_neigh);
    agg_kernel<<<(NN * 32 + 255) / 256, 256>>>(feat);
    dim3 cgrid(MBLK, 2);
    conv_mma_kernel<<<cgrid, 256, DYN_SMEM>>>(feat, b_conv, graph_id);
    bn_scale_kernel<<<1, HID>>>(gamma_conv, beta_conv);
    lp1_kernel<<<GG, HID>>>(W_lp, b_lp);
    lp2_kernel<<<GG, HID>>>(W_lp, b_lp, gamma_lp, beta_lp, out_p);
    lp3_kernel<<<GG, HID>>>(gamma_lp, beta_lp, out);
}

// round 8
// speedup vs baseline: 2.3041x; 1.0140x over previous
#include <cuda_runtime.h>
#include <cuda_fp16.h>
#include <cstdint>

#define NN  100000
#define EE  1000000
#define IND 128
#define HID 256
#define GG  64
#define BN_EPS 1e-5f

#define SCAN_B 1024
#define SCAN_NBLK ((NN + SCAN_B - 1) / SCAN_B)   // 98

#define TILE_M 64
#define MBLK ((NN + TILE_M - 1) / TILE_M)        // 1563

// W pre-scale: W*32, A/32 (keeps fp16 Wlo out of subnormal FTZ territory)
#define WSCALE 32.0f
#define AINV   0.03125f

// ---------------- scratch (static device globals; no allocation) ----------------
__device__ float g_agg[NN * IND];
__device__ int   g_deg[NN];
__device__ int   g_ptr[NN];
__device__ int   g_cur[NN];
__device__ int   g_esrc[EE];
__device__ int   g_bsum[SCAN_NBLK];
__device__ int   g_boff[SCAN_NBLK];
__device__ float g_poolraw[GG * HID];
__device__ int   g_cnt[GG];
__device__ float g_bnstats[8 * HID];
__device__ float g_z1[GG * HID];
__device__ float g_z2[GG * HID];
__device__ float g_p[GG * HID];
// fp16 W images (scaled by 32), row-major [K=256][N=256]
__device__ __half g_Whi[256 * 256];
__device__ __half g_Wlo[256 * 256];

// ---------------- helpers ----------------
__device__ __forceinline__ void redF1(float* addr, float v) {
    asm volatile("red.global.add.f32 [%0], %1;" :: "l"(addr), "f"(v) : "memory");
}
__device__ __forceinline__ void redI1(int* addr, int v) {
    asm volatile("red.global.add.s32 [%0], %1;" :: "l"(addr), "r"(v) : "memory");
}
__device__ __forceinline__ uint32_t hfu(__half h) {
    return (uint32_t)__half_as_ushort(h);
}
__device__ __forceinline__ uint32_t smem_u32(const void* p) {
    uint32_t a;
    asm("{ .reg .u64 t; cvta.to.shared.u64 t, %1; cvt.u32.u64 %0, t; }"
        : "=r"(a) : "l"(p));
    return a;
}
__device__ __forceinline__ void ldsm4(uint32_t* r, uint32_t a) {
    asm volatile("ldmatrix.sync.aligned.m8n8.x4.shared.b16 {%0,%1,%2,%3}, [%4];"
        : "=r"(r[0]), "=r"(r[1]), "=r"(r[2]), "=r"(r[3]) : "r"(a));
}
__device__ __forceinline__ void ldsm4t(uint32_t* r, uint32_t a) {
    asm volatile("ldmatrix.sync.aligned.m8n8.x4.trans.shared.b16 {%0,%1,%2,%3}, [%4];"
        : "=r"(r[0]), "=r"(r[1]), "=r"(r[2]), "=r"(r[3]) : "r"(a));
}
__device__ __forceinline__ void mma16816(float* d, const uint32_t* a, const uint32_t* b) {
    asm volatile("mma.sync.aligned.m16n8k16.row.col.f32.f16.f16.f32 "
        "{%0,%1,%2,%3}, {%4,%5,%6,%7}, {%8,%9}, {%0,%1,%2,%3};"
        : "+f"(d[0]), "+f"(d[1]), "+f"(d[2]), "+f"(d[3])
        : "r"(a[0]), "r"(a[1]), "r"(a[2]), "r"(a[3]), "r"(b[0]), "r"(b[1]));
}

// ---------------- K0: zero scratch + W prep (merged) ----------------
__global__ void prep_kernel(const float* __restrict__ W_self,
                            const float* __restrict__ W_neigh) {
    int idx = blockIdx.x * blockDim.x + threadIdx.x;   // 512*256 = 131072 threads
    if (idx < NN) g_deg[idx] = 0;
    if (idx < 65536) {
        int k = idx >> 8, n = idx & 255;
        float w = ((k < IND) ? W_self[k * HID + n] : W_neigh[(k - IND) * HID + n]) * WSCALE;
        __half hi = __float2half(w);
        __half lo = __float2half(w - __half2float(hi));
        g_Whi[idx] = hi;
        g_Wlo[idx] = lo;
    }
    if (idx < GG * HID) g_poolraw[idx] = 0.f;
    if (idx < GG) g_cnt[idx] = 0;
    if (idx < 6 * HID) g_bnstats[idx] = 0.f;
}

// ---------------- K0b: per-graph node counts ----------------
__global__ void count_kernel(const int* __restrict__ graph_id) {
    __shared__ int cnt[GG];
    int t = threadIdx.x;
    if (t < GG) cnt[t] = 0;
    __syncthreads();
    for (int i = blockIdx.x * blockDim.x + t; i < NN; i += gridDim.x * blockDim.x)
        atomicAdd(&cnt[__ldg(&graph_id[i])], 1);
    __syncthreads();
    if (t < GG && cnt[t]) atomicAdd(&g_cnt[t], cnt[t]);
}

// ---------------- CSR phases ----------------
__global__ void deg_kernel(const int* __restrict__ dst) {
    int e = blockIdx.x * blockDim.x + threadIdx.x;
    if (e < EE) redI1(&g_deg[__ldg(&dst[e])], 1);
}

__global__ __launch_bounds__(SCAN_B) void scan1_kernel() {
    __shared__ int sh[SCAN_B];
    int t = threadIdx.x;
    int i = blockIdx.x * SCAN_B + t;
    sh[t] = (i < NN) ? g_deg[i] : 0;
    __syncthreads();
#pragma unroll
    for (int s = SCAN_B / 2; s > 0; s >>= 1) {
        if (t < s) sh[t] += sh[t + s];
        __syncthreads();
    }
    if (t == 0) g_bsum[blockIdx.x] = sh[0];
}

__global__ __launch_bounds__(128) void scan2_kernel() {
    __shared__ int sh[128];
    int t = threadIdx.x;
    int v = (t < SCAN_NBLK) ? g_bsum[t] : 0;
    sh[t] = v;
    __syncthreads();
#pragma unroll
    for (int off = 1; off < 128; off <<= 1) {
        int x = (t >= off) ? sh[t - off] : 0;
        __syncthreads();
        sh[t] += x;
        __syncthreads();
    }
    if (t < SCAN_NBLK) g_boff[t] = sh[t] - v;
}

__global__ __launch_bounds__(SCAN_B) void scan3_kernel() {
    __shared__ int sh[SCAN_B];
    int t = threadIdx.x;
    int i = blockIdx.x * SCAN_B + t;
    int v = (i < NN) ? g_deg[i] : 0;
    sh[t] = v;
    __syncthreads();
#pragma unroll
    for (int off = 1; off < SCAN_B; off <<= 1) {
        int x = (t >= off) ? sh[t - off] : 0;
        __syncthreads();
        sh[t] += x;
        __syncthreads();
    }
    if (i < NN) {
        int pos = g_boff[blockIdx.x] + sh[t] - v;
        g_ptr[i] = pos;
        g_cur[i] = pos;
    }
}

__global__ void fill_kernel(const int* __restrict__ src,
                            const int* __restrict__ dst) {
    int e = blockIdx.x * blockDim.x + threadIdx.x;
    if (e >= EE) return;
    int d = __ldg(&dst[e]);
    int pos = atomicAdd(&g_cur[d], 1);
    g_esrc[pos] = __ldg(&src[e]);
}

// ---------------- K1: gather-aggregate (warp per node, no atomics) ----------------
__global__ __launch_bounds__(256) void agg_kernel(const float* __restrict__ feat) {
    int t = blockIdx.x * blockDim.x + threadIdx.x;
    int node = t >> 5;
    if (node >= NN) return;
    int lane = t & 31;
    int beg = __ldg(&g_ptr[node]);
    int d = __ldg(&g_deg[node]);
    float4 acc = make_float4(0.f, 0.f, 0.f, 0.f);
    for (int i = 0; i < d; i++) {
        int s = __ldg(&g_esrc[beg + i]);
        float4 v = __ldg(((const float4*)(feat + (size_t)s * IND)) + lane);
        acc.x += v.x; acc.y += v.y; acc.z += v.z; acc.w += v.w;
    }
    ((float4*)(g_agg + (size_t)node * IND))[lane] = acc;
}

// ---------------- K2: mma.sync fp16 2-term GEMM + relu + BN stats + pooling ------
// stage: Ah [64][80B] @0 (5120), Whi [32][528B] @5120 (16896), Wlo @22016 (16896)
// ST_SZ = 38912, double buffered (77824). C f32[64][264] aliases stage smem.
#define ST_SZ    38912
#define SOF_BH   5120
#define SOF_BL   22016
#define OFF_BSH  77824
#define OFF_INVD 78848
#define OFF_GIDS 79104
#define OFF_GRNG 79360
#define OFF_RS   79424
#define OFF_RQ   81472
#define DYN_SMEM 83520

__global__ __launch_bounds__(512) void conv_mma_kernel(
    const float* __restrict__ feat, const float* __restrict__ b_conv,
    const int* __restrict__ graph_id) {
    extern __shared__ char p0[];
    uint32_t sm = smem_u32(p0);
    float* s_bsh  = (float*)(p0 + OFF_BSH);
    float* s_invd = (float*)(p0 + OFF_INVD);
    int*   s_gids = (int*)(p0 + OFF_GIDS);
    int*   s_grng = (int*)(p0 + OFF_GRNG);
    float* s_rs   = (float*)(p0 + OFF_RS);
    float* s_rq   = (float*)(p0 + OFF_RQ);

    int tid = threadIdx.x;
    int wid = tid >> 5;
    int lane = tid & 31;
    int row0 = blockIdx.x * TILE_M;

    if (tid < 256) s_bsh[tid] = b_conv[tid];
    if (tid < TILE_M) {
        int node = row0 + tid;
        float dg = 1.f;
        int gid = -1;
        if (node < NN) {
            dg = fmaxf((float)g_deg[node], 1.f);
            gid = __ldg(&graph_id[node]);
        }
        s_invd[tid] = AINV / dg;        // fold 1/32 prescale into invd
        s_gids[tid] = gid;
    }
    __syncthreads();
    if (tid == 0) {
        int lo = s_gids[0], hi = lo;
#pragma unroll 1
        for (int i = 1; i < TILE_M; i++)
            if (s_gids[i] >= 0) hi = s_gids[i];
        s_grng[0] = lo; s_grng[1] = hi;
    }

    int wm = (wid >> 2) * 16;    // warp M offset (0/16/32/48)
    int wn = (wid & 3) * 64;     // warp N offset (0/64/128/192)

    float acc[8][4];
#pragma unroll
    for (int j = 0; j < 8; j++)
#pragma unroll
        for (int d = 0; d < 4; d++) acc[j][d] = 0.f;

    uint32_t Abase = sm + (wm + (lane & 15)) * 80 + (lane >> 4) * 16;
    uint32_t Bbase = sm + SOF_BH + (lane & 15) * 528 + (wn + (lane >> 4) * 8) * 2;

    float4 pa;
    uint4 pbh[2], pbl[2];

    auto load_g = [&](int kc) {
        {
            int r = tid >> 3, k4 = tid & 7;
            int node = row0 + r;
            float4 v = make_float4(0.f, 0.f, 0.f, 0.f);
            if (node < NN) {
                if (kc < 4)
                    v = __ldg((const float4*)(feat + (size_t)node * IND + kc * 32 + k4 * 4));
                else
                    v = *(const float4*)(g_agg + (size_t)node * IND + (kc - 4) * 32 + k4 * 4);
            }
            pa = v;
        }
#pragma unroll
        for (int it = 0; it < 2; it++) {
            int e = tid + it * 512;
            int kk = e >> 5, c = e & 31;
            int krow = kc * 32 + kk;
            pbh[it] = *(const uint4*)(g_Whi + (size_t)krow * 256 + c * 8);
            pbl[it] = *(const uint4*)(g_Wlo + (size_t)krow * 256 + c * 8);
        }
    };
    auto store_s = [&](int buf, int kc) {
        char* st = p0 + buf * ST_SZ;
        {
            int r = tid >> 3, k4 = tid & 7;
            float4 v = pa;
            float s = (kc >= 4) ? s_invd[r] : AINV;
            v.x *= s; v.y *= s; v.z *= s; v.w *= s;
            __half h0 = __float2half(v.x);
            __half h1 = __float2half(v.y);
            __half h2 = __float2half(v.z);
            __half h3 = __float2half(v.w);
            uint2 hu = make_uint2((hfu(h1) << 16) | hfu(h0), (hfu(h3) << 16) | hfu(h2));
            *(uint2*)(st + r * 80 + k4 * 8) = hu;
        }
#pragma unroll
        for (int it = 0; it < 2; it++) {
            int e = tid + it * 512;
            int kk = e >> 5, c = e & 31;
            *(uint4*)(st + SOF_BH + kk * 528 + c * 16) = pbh[it];
            *(uint4*)(st + SOF_BL + kk * 528 + c * 16) = pbl[it];
        }
    };
    auto compute = [&](int buf) {
        uint32_t so = buf * ST_SZ;
#pragma unroll
        for (int ks = 0; ks < 2; ks++) {
            uint32_t ab = Abase + so + ks * 32;
            uint32_t bb = Bbase + so + ks * 8448;   // ks*16*528
            uint32_t ah[4], bh[16], bl[16];
            ldsm4(ah, ab);
#pragma unroll
            for (int c = 0; c < 4; c++) {
                ldsm4t(&bh[4 * c], bb + c * 32);
                ldsm4t(&bl[4 * c], bb + 16896 + c * 32);
            }
#pragma unroll
            for (int j = 0; j < 8; j++) {
                mma16816(acc[j], ah, &bh[2 * j]);
                mma16816(acc[j], ah, &bl[2 * j]);
            }
        }
    };

    // -------- main loop: 8 K-chunks of 32, double-buffered --------
    load_g(0);
    store_s(0, 0);
    __syncthreads();
#pragma unroll 1
    for (int kc = 0; kc < 8; kc++) {
        if (kc < 7) load_g(kc + 1);
        compute(kc & 1);
        if (kc < 7) store_s((kc + 1) & 1, kc + 1);
        __syncthreads();
    }

    // -------- epilogue: C to smem, bias+relu, BN stats, pooling --------
    float* C = (float*)p0;   // [64][264]
#pragma unroll
    for (int j = 0; j < 8; j++) {
        int rr = wm + (lane >> 2);
        int cc = wn + j * 8 + (lane & 3) * 2;
        C[rr * 264 + cc]           = acc[j][0];
        C[rr * 264 + cc + 1]       = acc[j][1];
        C[(rr + 8) * 264 + cc]     = acc[j][2];
        C[(rr + 8) * 264 + cc + 1] = acc[j][3];
    }
    __syncthreads();

    int col = tid & 255, q = tid >> 8;   // half of rows (32 each)
    {
        float b = s_bsh[col];
        float sum = 0.f, sq = 0.f;
#pragma unroll 8
        for (int rr = q * 32; rr < q * 32 + 32; rr++) {
            float v = C[rr * 264 + col] + b;
            v = (s_gids[rr] >= 0) ? fmaxf(v, 0.f) : 0.f;
            C[rr * 264 + col] = v;
            sum += v; sq += v * v;
        }
        s_rs[q * 256 + col] = sum;
        s_rq[q * 256 + col] = sq;
    }
    __syncthreads();
    if (tid < 256) {
        redF1(&g_bnstats[tid], s_rs[tid] + s_rs[256 + tid]);
    } else {
        int c2 = tid - 256;
        redF1(&g_bnstats[256 + c2], s_rq[c2] + s_rq[256 + c2]);
    }
    int glo = s_grng[0], ghi = s_grng[1];
#pragma unroll 1
    for (int g = glo; g <= ghi; g++) {
        float pp = 0.f;
#pragma unroll 8
        for (int rr = q * 32; rr < q * 32 + 32; rr++)
            if (s_gids[rr] == g) pp += C[rr * 264 + col];
        __syncthreads();
        s_rs[q * 256 + col] = pp;
        __syncthreads();
        if (tid < 256)
            redF1(&g_poolraw[g * HID + tid], s_rs[tid] + s_rs[256 + tid]);
    }
}

// ---------------- K4: z1 = relu(pooled @ W_lp + b) + stats (BN fold inline) -------
__global__ __launch_bounds__(HID) void lp1_kernel(const float* __restrict__ W_lp,
                                                  const float* __restrict__ b_lp,
                                                  const float* __restrict__ gamma,
                                                  const float* __restrict__ beta) {
    __shared__ float row[HID];
    int g = blockIdx.x, c = threadIdx.x;
    float mean = g_bnstats[c] * (1.0f / NN);
    float var  = g_bnstats[256 + c] * (1.0f / NN) - mean * mean;
    float sc = gamma[c] * rsqrtf(var + BN_EPS);
    float sh = beta[c] - mean * sc;
    float cntf = (float)g_cnt[g];
    row[c] = fmaf(g_poolraw[g * HID + c], sc, cntf * sh);
    __syncthreads();
    float acc = b_lp[c];
#pragma unroll 8
    for (int k = 0; k < HID; k++) acc = fmaf(row[k], __ldg(&W_lp[k * HID + c]), acc);
    float r = fmaxf(acc, 0.f);
    g_z1[g * HID + c] = r;
    atomicAdd(&g_bnstats[512 + c], r);
    atomicAdd(&g_bnstats[768 + c], r * r);
}

// ---------------- K5: BN(z1) -> p, z2 = relu(p @ W_lp + b) + stats ----------------
__global__ __launch_bounds__(HID) void lp2_kernel(const float* __restrict__ W_lp,
                                                  const float* __restrict__ b_lp,
                                                  const float* __restrict__ gamma,
                                                  const float* __restrict__ beta,
                                                  float* __restrict__ out_p) {
    __shared__ float row[HID];
    int g = blockIdx.x, c = threadIdx.x;
    float r = g_z1[g * HID + c];
    float mean = g_bnstats[512 + c] * (1.f / GG);
    float var  = g_bnstats[768 + c] * (1.f / GG) - mean * mean;
    float p = (r - mean) * rsqrtf(var + BN_EPS) * gamma[c] + beta[c];
    out_p[g * HID + c] = p;
    row[c] = p;
    __syncthreads();
    float acc = b_lp[c];
#pragma unroll 8
    for (int k = 0; k < HID; k++) acc = fmaf(row[k], __ldg(&W_lp[k * HID + c]), acc);
    float r2 = fmaxf(acc, 0.f);
    g_z2[g * HID + c] = r2;
    atomicAdd(&g_bnstats[1024 + c], r2);
    atomicAdd(&g_bnstats[1280 + c], r2 * r2);
}

// ---------------- K6: BN(z2) + log_softmax ----------------
__global__ __launch_bounds__(HID) void lp3_kernel(const float* __restrict__ gamma,
                                                  const float* __restrict__ beta,
                                                  float* __restrict__ out) {
    __shared__ float buf[HID];
    int g = blockIdx.x, c = threadIdx.x;
    float r = g_z2[g * HID + c];
    float mean = g_bnstats[1024 + c] * (1.f / GG);
    float var  = g_bnstats[1280 + c] * (1.f / GG) - mean * mean;
    float o = (r - mean) * rsqrtf(var + BN_EPS) * gamma[c] + beta[c];
    buf[c] = o;
    __syncthreads();
    for (int s = 128; s > 0; s >>= 1) {
        if (c < s) buf[c] = fmaxf(buf[c], buf[c + s]);
        __syncthreads();
    }
    float m = buf[0];
    __syncthreads();
    float e = expf(o - m);
    buf[c] = e;
    __syncthreads();
    for (int s = 128; s > 0; s >>= 1) {
        if (c < s) buf[c] += buf[c + s];
        __syncthreads();
    }
    float lse = logf(buf[0]);
    out[g * HID + c] = o - m - lse;
}

// ---------------- launch ----------------
extern "C" void kernel_launch(void* const* d_in, const int* in_sizes, int n_in,
                              void* d_out, int out_size) {
    const float* feat       = (const float*)d_in[0];
    const float* W_self     = (const float*)d_in[1];
    const float* W_neigh    = (const float*)d_in[2];
    const float* b_conv     = (const float*)d_in[3];
    const float* gamma_conv = (const float*)d_in[4];
    const float* beta_conv  = (const float*)d_in[5];
    const float* W_lp       = (const float*)d_in[6];
    const float* b_lp       = (const float*)d_in[7];
    const float* gamma_lp   = (const float*)d_in[8];
    const float* beta_lp    = (const float*)d_in[9];
    const int*   src        = (const int*)d_in[10];
    const int*   dst        = (const int*)d_in[11];
    const int*   graph_id   = (const int*)d_in[12];
    float* out = (float*)d_out;

    float* out_p;
    if (out_size >= 2 * GG * HID) {
        out_p = out + GG * HID;
    } else {
        void* pp = nullptr;
        cudaGetSymbolAddress(&pp, g_p);
        out_p = (float*)pp;
    }

    cudaFuncSetAttribute(conv_mma_kernel,
                         cudaFuncAttributeMaxDynamicSharedMemorySize, DYN_SMEM);

    prep_kernel<<<512, 256>>>(W_self, W_neigh);
    count_kernel<<<128, 1024>>>(graph_id);
    deg_kernel<<<(EE + 255) / 256, 256>>>(dst);
    scan1_kernel<<<SCAN_NBLK, SCAN_B>>>();
    scan2_kernel<<<1, 128>>>();
    scan3_kernel<<<SCAN_NBLK, SCAN_B>>>();
    fill_kernel<<<(EE + 255) / 256, 256>>>(src, dst);
    agg_kernel<<<(NN * 32 + 255) / 256, 256>>>(feat);
    conv_mma_kernel<<<MBLK, 512, DYN_SMEM>>>(feat, b_conv, graph_id);
    lp1_kernel<<<GG, HID>>>(W_lp, b_lp, gamma_conv, beta_conv);
    lp2_kernel<<<GG, HID>>>(W_lp, b_lp, gamma_lp, beta_lp, out_p);
    lp3_kernel<<<GG, HID>>>(gamma_lp, beta_lp, out);
}

// round 10
// speedup vs baseline: 2.6326x; 1.1426x over previous
#include <cuda_runtime.h>
#include <cuda_fp16.h>
#include <cstdint>

#define NN  100000
#define EE  1000000
#define IND 128
#define HID 256
#define GG  64
#define BN_EPS 1e-5f

#define SCAN_B 1024
#define SCAN_NBLK ((NN + SCAN_B - 1) / SCAN_B)   // 98

#define TILE_M 128
#define MBLK ((NN + TILE_M - 1) / TILE_M)        // 782

#define WSCALE 32.0f
#define AINV   0.03125f

// ---------------- scratch (static device globals; no allocation) ----------------
__device__ __half g_feath[(NN + TILE_M) * IND];  // feat * (1/32), fp16, padded
__device__ __half g_aggh[(NN + TILE_M) * IND];   // h_neigh * (1/32), fp16, padded
__device__ int   g_deg[NN];
__device__ int   g_ptr[NN];
__device__ int   g_cur[NN];
__device__ int   g_esrc[EE];
__device__ int   g_bsum[SCAN_NBLK];
__device__ int   g_boff[SCAN_NBLK];
__device__ float g_poolraw[GG * HID];
__device__ int   g_cnt[GG];
__device__ float g_bnstats[8 * HID];
__device__ float g_z1[GG * HID];
__device__ float g_z2[GG * HID];
__device__ float g_p[GG * HID];
__device__ __half g_Whi[256 * 256];              // W * 32 hi
__device__ __half g_Wlo[256 * 256];              // W * 32 lo

// ---------------- helpers ----------------
__device__ __forceinline__ void redF1(float* addr, float v) {
    asm volatile("red.global.add.f32 [%0], %1;" :: "l"(addr), "f"(v) : "memory");
}
__device__ __forceinline__ void redI1(int* addr, int v) {
    asm volatile("red.global.add.s32 [%0], %1;" :: "l"(addr), "r"(v) : "memory");
}
__device__ __forceinline__ uint32_t smem_u32(const void* p) {
    uint32_t a;
    asm("{ .reg .u64 t; cvta.to.shared.u64 t, %1; cvt.u32.u64 %0, t; }"
        : "=r"(a) : "l"(p));
    return a;
}
__device__ __forceinline__ void ldsm4(uint32_t* r, uint32_t a) {
    asm volatile("ldmatrix.sync.aligned.m8n8.x4.shared.b16 {%0,%1,%2,%3}, [%4];"
        : "=r"(r[0]), "=r"(r[1]), "=r"(r[2]), "=r"(r[3]) : "r"(a));
}
__device__ __forceinline__ void ldsm4t(uint32_t* r, uint32_t a) {
    asm volatile("ldmatrix.sync.aligned.m8n8.x4.trans.shared.b16 {%0,%1,%2,%3}, [%4];"
        : "=r"(r[0]), "=r"(r[1]), "=r"(r[2]), "=r"(r[3]) : "r"(a));
}
__device__ __forceinline__ void mma16816(float* d, const uint32_t* a, const uint32_t* b) {
    asm volatile("mma.sync.aligned.m16n8k16.row.col.f32.f16.f16.f32 "
        "{%0,%1,%2,%3}, {%4,%5,%6,%7}, {%8,%9}, {%0,%1,%2,%3};"
        : "+f"(d[0]), "+f"(d[1]), "+f"(d[2]), "+f"(d[3])
        : "r"(a[0]), "r"(a[1]), "r"(a[2]), "r"(a[3]), "r"(b[0]), "r"(b[1]));
}
__device__ __forceinline__ void cpa16(uint32_t d, const void* s) {
    asm volatile("cp.async.cg.shared.global [%0], [%1], 16;" :: "r"(d), "l"(s));
}
__device__ __forceinline__ void cpa8(uint32_t d, const void* s) {
    asm volatile("cp.async.ca.shared.global [%0], [%1], 8;" :: "r"(d), "l"(s));
}
#define CP_COMMIT() asm volatile("cp.async.commit_group;" ::: "memory")
#define CP_WAIT0()  asm volatile("cp.async.wait_group 0;" ::: "memory")

// ---------------- K0: zero scratch + W prep + pad zero ----------------
__global__ void prep_kernel(const float* __restrict__ W_self,
                            const float* __restrict__ W_neigh) {
    int idx = blockIdx.x * blockDim.x + threadIdx.x;   // 512*256 = 131072
    if (idx < NN) g_deg[idx] = 0;
    if (idx < 65536) {
        int k = idx >> 8, n = idx & 255;
        float w = ((k < IND) ? W_self[k * HID + n] : W_neigh[(k - IND) * HID + n]) * WSCALE;
        __half hi = __float2half(w);
        __half lo = __float2half(w - __half2float(hi));
        g_Whi[idx] = hi;
        g_Wlo[idx] = lo;
    }
    if (idx < TILE_M * IND) {                          // zero pad rows
        g_feath[NN * IND + idx] = __ushort_as_half(0);
        g_aggh[NN * IND + idx] = __ushort_as_half(0);
    }
    if (idx < GG * HID) g_poolraw[idx] = 0.f;
    if (idx < GG) g_cnt[idx] = 0;
    if (idx < 6 * HID) g_bnstats[idx] = 0.f;
}

// ---------------- K0c: feat -> fp16*(1/32) image ----------------
__global__ void feath_kernel(const float* __restrict__ feat) {
    int idx = blockIdx.x * blockDim.x + threadIdx.x;   // NN*32 float4 units
    if (idx >= NN * (IND / 4)) return;
    float4 v = __ldg(((const float4*)feat) + idx);
    __half h0 = __float2half(v.x * AINV);
    __half h1 = __float2half(v.y * AINV);
    __half h2 = __float2half(v.z * AINV);
    __half h3 = __float2half(v.w * AINV);
    uint2 u;
    u.x = ((uint32_t)__half_as_ushort(h1) << 16) | __half_as_ushort(h0);
    u.y = ((uint32_t)__half_as_ushort(h3) << 16) | __half_as_ushort(h2);
    ((uint2*)g_feath)[idx] = u;
}

// ---------------- K0b: per-graph node counts ----------------
__global__ void count_kernel(const int* __restrict__ graph_id) {
    __shared__ int cnt[GG];
    int t = threadIdx.x;
    if (t < GG) cnt[t] = 0;
    __syncthreads();
    for (int i = blockIdx.x * blockDim.x + t; i < NN; i += gridDim.x * blockDim.x)
        atomicAdd(&cnt[__ldg(&graph_id[i])], 1);
    __syncthreads();
    if (t < GG && cnt[t]) atomicAdd(&g_cnt[t], cnt[t]);
}

// ---------------- CSR phases ----------------
__global__ void deg_kernel(const int* __restrict__ dst) {
    int e = blockIdx.x * blockDim.x + threadIdx.x;
    if (e < EE) redI1(&g_deg[__ldg(&dst[e])], 1);
}

__global__ __launch_bounds__(SCAN_B) void scan1_kernel() {
    __shared__ int sh[SCAN_B];
    int t = threadIdx.x;
    int i = blockIdx.x * SCAN_B + t;
    sh[t] = (i < NN) ? g_deg[i] : 0;
    __syncthreads();
#pragma unroll
    for (int s = SCAN_B / 2; s > 0; s >>= 1) {
        if (t < s) sh[t] += sh[t + s];
        __syncthreads();
    }
    if (t == 0) g_bsum[blockIdx.x] = sh[0];
}

__global__ __launch_bounds__(128) void scan2_kernel() {
    __shared__ int sh[128];
    int t = threadIdx.x;
    int v = (t < SCAN_NBLK) ? g_bsum[t] : 0;
    sh[t] = v;
    __syncthreads();
#pragma unroll
    for (int off = 1; off < 128; off <<= 1) {
        int x = (t >= off) ? sh[t - off] : 0;
        __syncthreads();
        sh[t] += x;
        __syncthreads();
    }
    if (t < SCAN_NBLK) g_boff[t] = sh[t] - v;
}

__global__ __launch_bounds__(SCAN_B) void scan3_kernel() {
    __shared__ int sh[SCAN_B];
    int t = threadIdx.x;
    int i = blockIdx.x * SCAN_B + t;
    int v = (i < NN) ? g_deg[i] : 0;
    sh[t] = v;
    __syncthreads();
#pragma unroll
    for (int off = 1; off < SCAN_B; off <<= 1) {
        int x = (t >= off) ? sh[t - off] : 0;
        __syncthreads();
        sh[t] += x;
        __syncthreads();
    }
    if (i < NN) {
        int pos = g_boff[blockIdx.x] + sh[t] - v;
        g_ptr[i] = pos;
        g_cur[i] = pos;
    }
}

__global__ void fill_kernel(const int* __restrict__ src,
                            const int* __restrict__ dst) {
    int e = blockIdx.x * blockDim.x + threadIdx.x;
    if (e >= EE) return;
    int d = __ldg(&dst[e]);
    int pos = atomicAdd(&g_cur[d], 1);
    g_esrc[pos] = __ldg(&src[e]);
}

// ---------------- K1: gather-aggregate from fp16 image (warp per node) ----------
__global__ __launch_bounds__(256) void agg_kernel() {
    int t = blockIdx.x * blockDim.x + threadIdx.x;
    int node = t >> 5;
    if (node >= NN) return;
    int lane = t & 31;
    int beg = __ldg(&g_ptr[node]);
    int d = __ldg(&g_deg[node]);
    float2 a0 = make_float2(0.f, 0.f), a1 = make_float2(0.f, 0.f);
    const uint2* base = (const uint2*)g_feath;   // 32 uint2 per row
    for (int i = 0; i < d; i++) {
        int s = __ldg(&g_esrc[beg + i]);
        uint2 u = __ldg(base + (size_t)s * 32 + lane);
        float2 f0 = __half22float2(*(__half2*)&u.x);
        float2 f1 = __half22float2(*(__half2*)&u.y);
        a0.x += f0.x; a0.y += f0.y; a1.x += f1.x; a1.y += f1.y;
    }
    float sc = 1.f / fmaxf((float)d, 1.f);       // feath already has the 1/32
    __half h0 = __float2half(a0.x * sc);
    __half h1 = __float2half(a0.y * sc);
    __half h2 = __float2half(a1.x * sc);
    __half h3 = __float2half(a1.y * sc);
    uint2 o;
    o.x = ((uint32_t)__half_as_ushort(h1) << 16) | __half_as_ushort(h0);
    o.y = ((uint32_t)__half_as_ushort(h3) << 16) | __half_as_ushort(h2);
    ((uint2*)g_aggh)[(size_t)node * 32 + lane] = o;
}

// ---------------- K2: mma.sync fp16 2-term GEMM, cp.async staged, M=128 N=256 ---
// stage: A [128][80B] @0 (10240), Whi [32][528B] @10240 (16896), Wlo @27136 (16896)
// ST_SZ=44032, double buffered (88064). Epilogue aliases: C half[128][264] @0
// (67584), colsum @67584, colsq @71680, pool @75776 (8192).
#define ST_SZ    44032
#define SOF_WH   10240
#define SOF_WL   27136
#define OFF_CS   67584
#define OFF_CQ   71680
#define OFF_POOL 75776
#define OFF_BSH  88064
#define OFF_GIDS 89088
#define OFF_GRNG 89600
#define DYN_SMEM 89616

__global__ __launch_bounds__(1024, 1) void conv_mma_kernel(
    const float* __restrict__ b_conv, const int* __restrict__ graph_id) {
    extern __shared__ char p0[];
    uint32_t sm = smem_u32(p0);
    float* s_bsh  = (float*)(p0 + OFF_BSH);
    int*   s_gids = (int*)(p0 + OFF_GIDS);
    int*   s_grng = (int*)(p0 + OFF_GRNG);

    int tid = threadIdx.x;
    int wid = tid >> 5;
    int lane = tid & 31;
    int row0 = blockIdx.x * TILE_M;

    if (tid < 256) s_bsh[tid] = b_conv[tid];
    if (tid < TILE_M) {
        int node = row0 + tid;
        s_gids[tid] = (node < NN) ? __ldg(&graph_id[node]) : -1;
    }
    __syncthreads();
    if (tid == 0) {
        int lo = s_gids[0], hi = lo;
#pragma unroll 1
        for (int i = 1; i < TILE_M; i++)
            if (s_gids[i] >= 0) hi = s_gids[i];
        s_grng[0] = lo; s_grng[1] = hi;
    }

    int wm = (wid >> 2) * 16;    // warp M offset (0..112)
    int wn = (wid & 3) * 64;     // warp N offset (0/64/128/192)

    float acc[8][4];
#pragma unroll
    for (int j = 0; j < 8; j++)
#pragma unroll
        for (int d = 0; d < 4; d++) acc[j][d] = 0.f;

    uint32_t Abase = sm + (wm + (lane & 15)) * 80 + (lane >> 4) * 16;
    uint32_t Bbase = sm + SOF_WH + (lane & 15) * 528 + (wn + (lane >> 4) * 8) * 2;

    auto stage = [&](int kc, int buf) {
        uint32_t st = sm + buf * ST_SZ;
        // A: 8B per thread (4 halfs), already fp16 pre-scaled
        {
            int r = tid >> 3, u = tid & 7;
            const __half* srcb = (kc < 4) ? g_feath : g_aggh;
            int kof = (kc & 3) * 32;
            cpa8(st + r * 80 + u * 8,
                 srcb + (size_t)(row0 + r) * IND + kof + u * 4);
        }
        // W hi/lo: 16B per thread each
        {
            int kk = tid >> 5, c = tid & 31;
            size_t so = (size_t)(kc * 32 + kk) * 256 + c * 8;
            cpa16(st + SOF_WH + kk * 528 + c * 16, g_Whi + so);
            cpa16(st + SOF_WL + kk * 528 + c * 16, g_Wlo + so);
        }
    };
    auto compute = [&](int buf) {
        uint32_t so = buf * ST_SZ;
#pragma unroll
        for (int ks = 0; ks < 2; ks++) {
            uint32_t ab = Abase + so + ks * 32;
            uint32_t bb = Bbase + so + ks * 8448;   // ks*16*528
            uint32_t ah[4], f[4];
            ldsm4(ah, ab);
#pragma unroll
            for (int c = 0; c < 4; c++) {
                ldsm4t(f, bb + c * 32);
                mma16816(acc[2 * c], ah, f);
                mma16816(acc[2 * c + 1], ah, f + 2);
                ldsm4t(f, bb + 16896 + c * 32);
                mma16816(acc[2 * c], ah, f);
                mma16816(acc[2 * c + 1], ah, f + 2);
            }
        }
    };

    // -------- main loop: 8 K-chunks of 32, double-buffered cp.async --------
    stage(0, 0);
    CP_COMMIT();
    CP_WAIT0();
    __syncthreads();
#pragma unroll 1
    for (int kc = 0; kc < 8; kc++) {
        if (kc < 7) { stage(kc + 1, (kc + 1) & 1); CP_COMMIT(); }
        compute(kc & 1);
        if (kc < 7) CP_WAIT0();
        __syncthreads();
    }

    // -------- epilogue --------
    __half* C  = (__half*)p0;                 // [128][264]
    float* s_cs = (float*)(p0 + OFF_CS);      // [4][256]
    float* s_cq = (float*)(p0 + OFF_CQ);      // [4][256]
    float* s_pl = (float*)(p0 + OFF_POOL);    // [8][256]
#pragma unroll
    for (int j = 0; j < 8; j++) {
        int r0 = wm + (lane >> 2);
        int c = wn + j * 8 + (lane & 3) * 2;
        __half2 lo2 = __floats2half2_rn(acc[j][0], acc[j][1]);
        __half2 hi2 = __floats2half2_rn(acc[j][2], acc[j][3]);
        *(__half2*)&C[r0 * 264 + c] = lo2;
        *(__half2*)&C[(r0 + 8) * 264 + c] = hi2;
    }
    __syncthreads();
    // zero pool slots
    ((float*)s_pl)[tid] = 0.f;
    ((float*)s_pl)[tid + 1024] = 0.f;
    __syncthreads();

    int col = tid & 255, q = tid >> 8;        // quarter of rows (32 each)
    int glo = s_grng[0], ghi = s_grng[1];
    {
        float b = s_bsh[col];
        float sum = 0.f, sq = 0.f;
        int curg = -1;
        float run = 0.f;
#pragma unroll 4
        for (int rr = q * 32; rr < q * 32 + 32; rr++) {
            int gd = s_gids[rr];
            float v = __half2float(C[rr * 264 + col]) + b;
            v = (gd >= 0) ? fmaxf(v, 0.f) : 0.f;
            C[rr * 264 + col] = __float2half(v);
            sum += v; sq += v * v;
            if (gd != curg) {
                int slot = curg - glo;
                if (curg >= 0 && slot < 8) atomicAdd(&s_pl[slot * 256 + col], run);
                run = 0.f; curg = gd;
            }
            run += v;
        }
        int slot = curg - glo;
        if (curg >= 0 && slot < 8) atomicAdd(&s_pl[slot * 256 + col], run);
        s_cs[q * 256 + col] = sum;
        s_cq[q * 256 + col] = sq;
    }
    __syncthreads();
    if (tid < 256) {
        float s = s_cs[col] + s_cs[256 + col] + s_cs[512 + col] + s_cs[768 + col];
        redF1(&g_bnstats[col], s);
#pragma unroll 1
        for (int t = 0; t < 8; t++) {
            int g = glo + t;
            if (g <= ghi) redF1(&g_poolraw[g * HID + col], s_pl[t * 256 + col]);
        }
    } else if (tid < 512) {
        int c2 = tid - 256;
        float s = s_cq[c2] + s_cq[256 + c2] + s_cq[512 + c2] + s_cq[768 + c2];
        redF1(&g_bnstats[256 + c2], s);
    }
    // rare: block spans more than 8 graphs
#pragma unroll 1
    for (int p = 1; glo + 8 * p <= ghi; p++) {
        __syncthreads();
        ((float*)s_pl)[tid] = 0.f;
        ((float*)s_pl)[tid + 1024] = 0.f;
        __syncthreads();
        int base = glo + 8 * p;
        int curg = -1;
        float run = 0.f;
#pragma unroll 1
        for (int rr = q * 32; rr < q * 32 + 32; rr++) {
            int gd = s_gids[rr];
            float v = __half2float(C[rr * 264 + col]);
            if (gd != curg) {
                int slot = curg - base;
                if (slot >= 0 && slot < 8) atomicAdd(&s_pl[slot * 256 + col], run);
                run = 0.f; curg = gd;
            }
            run += v;
        }
        int slot = curg - base;
        if (slot >= 0 && slot < 8) atomicAdd(&s_pl[slot * 256 + col], run);
        __syncthreads();
        if (tid < 256) {
#pragma unroll 1
            for (int t = 0; t < 8; t++) {
                int g = base + t;
                if (g <= ghi) redF1(&g_poolraw[g * HID + col], s_pl[t * 256 + col]);
            }
        }
    }
}

// ---------------- K4: z1 = relu(pooled @ W_lp + b) + stats (BN fold inline) -------
__global__ __launch_bounds__(HID) void lp1_kernel(const float* __restrict__ W_lp,
                                                  const float* __restrict__ b_lp,
                                                  const float* __restrict__ gamma,
                                                  const float* __restrict__ beta) {
    __shared__ float row[HID];
    int g = blockIdx.x, c = threadIdx.x;
    float mean = g_bnstats[c] * (1.0f / NN);
    float var  = g_bnstats[256 + c] * (1.0f / NN) - mean * mean;
    float sc = gamma[c] * rsqrtf(var + BN_EPS);
    float sh = beta[c] - mean * sc;
    float cntf = (float)g_cnt[g];
    row[c] = fmaf(g_poolraw[g * HID + c], sc, cntf * sh);
    __syncthreads();
    float acc = b_lp[c];
#pragma unroll 8
    for (int k = 0; k < HID; k++) acc = fmaf(row[k], __ldg(&W_lp[k * HID + c]), acc);
    float r = fmaxf(acc, 0.f);
    g_z1[g * HID + c] = r;
    atomicAdd(&g_bnstats[512 + c], r);
    atomicAdd(&g_bnstats[768 + c], r * r);
}

// ---------------- K5: BN(z1) -> p, z2 = relu(p @ W_lp + b) + stats ----------------
__global__ __launch_bounds__(HID) void lp2_kernel(const float* __restrict__ W_lp,
                                                  const float* __restrict__ b_lp,
                                                  const float* __restrict__ gamma,
                                                  const float* __restrict__ beta,
                                                  float* __restrict__ out_p) {
    __shared__ float row[HID];
    int g = blockIdx.x, c = threadIdx.x;
    float r = g_z1[g * HID + c];
    float mean = g_bnstats[512 + c] * (1.f / GG);
    float var  = g_bnstats[768 + c] * (1.f / GG) - mean * mean;
    float p = (r - mean) * rsqrtf(var + BN_EPS) * gamma[c] + beta[c];
    out_p[g * HID + c] = p;
    row[c] = p;
    __syncthreads();
    float acc = b_lp[c];
#pragma unroll 8
    for (int k = 0; k < HID; k++) acc = fmaf(row[k], __ldg(&W_lp[k * HID + c]), acc);
    float r2 = fmaxf(acc, 0.f);
    g_z2[g * HID + c] = r2;
    atomicAdd(&g_bnstats[1024 + c], r2);
    atomicAdd(&g_bnstats[1280 + c], r2 * r2);
}

// ---------------- K6: BN(z2) + log_softmax ----------------
__global__ __launch_bounds__(HID) void lp3_kernel(const float* __restrict__ gamma,
                                                  const float* __restrict__ beta,
                                                  float* __restrict__ out) {
    __shared__ float buf[HID];
    int g = blockIdx.x, c = threadIdx.x;
    float r = g_z2[g * HID + c];
    float mean = g_bnstats[1024 + c] * (1.f / GG);
    float var  = g_bnstats[1280 + c] * (1.f / GG) - mean * mean;
    float o = (r - mean) * rsqrtf(var + BN_EPS) * gamma[c] + beta[c];
    buf[c] = o;
    __syncthreads();
    for (int s = 128; s > 0; s >>= 1) {
        if (c < s) buf[c] = fmaxf(buf[c], buf[c + s]);
        __syncthreads();
    }
    float m = buf[0];
    __syncthreads();
    float e = expf(o - m);
    buf[c] = e;
    __syncthreads();
    for (int s = 128; s > 0; s >>= 1) {
        if (c < s) buf[c] += buf[c + s];
        __syncthreads();
    }
    float lse = logf(buf[0]);
    out[g * HID + c] = o - m - lse;
}

// ---------------- launch ----------------
extern "C" void kernel_launch(void* const* d_in, const int* in_sizes, int n_in,
                              void* d_out, int out_size) {
    const float* feat       = (const float*)d_in[0];
    const float* W_self     = (const float*)d_in[1];
    const float* W_neigh    = (const float*)d_in[2];
    const float* b_conv     = (const float*)d_in[3];
    const float* gamma_conv = (const float*)d_in[4];
    const float* beta_conv  = (const float*)d_in[5];
    const float* W_lp       = (const float*)d_in[6];
    const float* b_lp       = (const float*)d_in[7];
    const float* gamma_lp   = (const float*)d_in[8];
    const float* beta_lp    = (const float*)d_in[9];
    const int*   src        = (const int*)d_in[10];
    const int*   dst        = (const int*)d_in[11];
    const int*   graph_id   = (const int*)d_in[12];
    float* out = (float*)d_out;

    float* out_p;
    if (out_size >= 2 * GG * HID) {
        out_p = out + GG * HID;
    } else {
        void* pp = nullptr;
        cudaGetSymbolAddress(&pp, g_p);
        out_p = (float*)pp;
    }

    cudaFuncSetAttribute(conv_mma_kernel,
                         cudaFuncAttributeMaxDynamicSharedMemorySize, DYN_SMEM);

    prep_kernel<<<512, 256>>>(W_self, W_neigh);
    feath_kernel<<<(NN * (IND / 4) + 255) / 256, 256>>>(feat);
    count_kernel<<<128, 1024>>>(graph_id);
    deg_kernel<<<(EE + 255) / 256, 256>>>(dst);
    scan1_kernel<<<SCAN_NBLK, SCAN_B>>>();
    scan2_kernel<<<1, 128>>>();
    scan3_kernel<<<SCAN_NBLK, SCAN_B>>>();
    fill_kernel<<<(EE + 255) / 256, 256>>>(src, dst);
    agg_kernel<<<(NN * 32 + 255) / 256, 256>>>();
    conv_mma_kernel<<<MBLK, 1024, DYN_SMEM>>>(b_conv, graph_id);
    lp1_kernel<<<GG, HID>>>(W_lp, b_lp, gamma_conv, beta_conv);
    lp2_kernel<<<GG, HID>>>(W_lp, b_lp, gamma_lp, beta_lp, out_p);
    lp3_kernel<<<GG, HID>>>(gamma_lp, beta_lp, out);
}